// round 6
// baseline (speedup 1.0000x reference)
#include <cuda_runtime.h>
#include <math.h>
#include <stdint.h>

#define NP    65534
#define NTOK  (NP*4)          // 262136 tokens
#define GH    180
#define GW    360
#define NCELL (GH*GW)         // 64800
#define CLN   512

// ---------------- scratch (device globals: no allocation allowed) ----------------
__device__ float g_feat[(size_t)NP*80];      // 75 used + zero pad to 80 (tf32-rounded)
__device__ int   g_flat[NP];
__device__ float g_h   [(size_t)NTOK*128];   // transformer state (fp32)
__device__ float g_qkv [(size_t)NTOK*384];
__device__ float g_y   [(size_t)NP*512];
__device__ float g_cnt [NCELL];
__device__ float g_wt  [696320];             // transposed, tf32-rounded weights

// ---------------- small PTX helpers ----------------
__device__ __forceinline__ uint32_t f2tf32(float x) {
    uint32_t r;
    asm("cvt.rna.tf32.f32 %0, %1;" : "=r"(r) : "f"(x));
    return r;
}
__device__ __forceinline__ float tf32r(float x) { return __uint_as_float(f2tf32(x)); }

__device__ __forceinline__ void cpasync16(uint32_t dst, const float* src, bool pred) {
    int sz = pred ? 16 : 0;      // sz=0 => zero-fill 16 bytes
    asm volatile("cp.async.cg.shared.global [%0], [%1], 16, %2;\n"
                 :: "r"(dst), "l"(src), "r"(sz));
}
__device__ __forceinline__ void cp_commit() {
    asm volatile("cp.async.commit_group;\n" ::);
}
__device__ __forceinline__ void ldm4(uint32_t& r0, uint32_t& r1, uint32_t& r2, uint32_t& r3, uint32_t addr) {
    asm volatile("ldmatrix.sync.aligned.m8n8.x4.shared.b16 {%0,%1,%2,%3}, [%4];\n"
                 : "=r"(r0), "=r"(r1), "=r"(r2), "=r"(r3) : "r"(addr));
}
__device__ __forceinline__ void mma_tf32(float* c, const uint32_t* a, uint32_t b0, uint32_t b1) {
    asm volatile("mma.sync.aligned.m16n8k8.row.col.f32.tf32.tf32.f32 "
                 "{%0,%1,%2,%3}, {%4,%5,%6,%7}, {%8,%9}, {%0,%1,%2,%3};\n"
                 : "+f"(c[0]), "+f"(c[1]), "+f"(c[2]), "+f"(c[3])
                 : "r"(a[0]), "r"(a[1]), "r"(a[2]), "r"(a[3]), "r"(b0), "r"(b1));
}
__device__ __forceinline__ float gelu_t(float u) {
    return 0.5f * u * (1.0f + tanhf(0.7978845608028654f * (u + 0.044715f * u * u * u)));
}

#define SMS 36
#define STG (128*SMS)   // 4608 floats = one 128x32 chunk

// 128x128x32 mma on one k-chunk: aBase/bBase = smem byte addr of [128][36] chunk
template<bool CVT>
__device__ __forceinline__ void mma_tile_128(uint32_t aBase, uint32_t bBase,
                                             int ra0, int rb0, int lkof,
                                             float acc[2][8][4]) {
    #pragma unroll
    for (int kk = 0; kk < 32; kk += 8) {
        uint32_t a[2][4];
        #pragma unroll
        for (int mi = 0; mi < 2; mi++) {
            ldm4(a[mi][0], a[mi][1], a[mi][2], a[mi][3],
                 aBase + (uint32_t)(((ra0 + mi * 16) * SMS + kk + lkof) * 4));
            if (CVT) {
                #pragma unroll
                for (int r = 0; r < 4; r++) a[mi][r] = f2tf32(__uint_as_float(a[mi][r]));
            }
        }
        uint32_t b0[8], b1[8];
        #pragma unroll
        for (int np = 0; np < 4; np++) {
            uint32_t r0, r1, r2, r3;
            ldm4(r0, r1, r2, r3, bBase + (uint32_t)(((rb0 + np * 16) * SMS + kk + lkof) * 4));
            b0[2*np] = r0; b0[2*np+1] = r1;
            b1[2*np] = r2; b1[2*np+1] = r3;
        }
        #pragma unroll
        for (int mi = 0; mi < 2; mi++)
            #pragma unroll
            for (int ni = 0; ni < 8; ni++)
                mma_tf32(acc[mi][ni], a[mi], b0[ni], b1[ni]);
    }
}

// shared epilogue for 128-row tiles, warp layout 4x2 (warp tile 32x64)
template<int EPI>   // 0=bias, 1=bias+residual, 2=bias+gelu(tf32r)
__device__ __forceinline__ void epi128(float acc[2][8][4], const float* __restrict__ bias,
                                       const float* __restrict__ R, float* __restrict__ C,
                                       int M, int N, int bm, int bn, int wm, int wn, int lane) {
    const int row0 = bm + wm * 32 + (lane >> 2);
    const int col0 = bn + wn * 64 + (lane & 3) * 2;
    #pragma unroll
    for (int mi = 0; mi < 2; mi++) {
        #pragma unroll
        for (int half = 0; half < 2; half++) {
            int gm = row0 + mi * 16 + half * 8;
            if (gm >= M) continue;
            #pragma unroll
            for (int ni = 0; ni < 8; ni++) {
                int gn = col0 + ni * 8;
                float v0 = acc[mi][ni][half*2 + 0] + bias[gn];
                float v1 = acc[mi][ni][half*2 + 1] + bias[gn + 1];
                if (EPI == 1) {
                    const float2 rr = *(const float2*)(R + (size_t)gm * N + gn);
                    v0 += rr.x; v1 += rr.y;
                }
                if (EPI == 2) { v0 = tf32r(gelu_t(v0)); v1 = tf32r(gelu_t(v1)); }
                float2 o; o.x = v0; o.y = v1;
                *(float2*)(C + (size_t)gm * N + gn) = o;
            }
        }
    }
}

// LayerNorm the 128x128 A tile in smem (4 chunks of [128][36]); output tf32-rounded
__device__ __forceinline__ void ln_smem(float* As, const float* __restrict__ s,
                                        const float* __restrict__ b, int w, int lane) {
    float sc[4], bc[4];
    #pragma unroll
    for (int c = 0; c < 4; c++) { sc[c] = s[c*32 + lane]; bc[c] = b[c*32 + lane]; }
    #pragma unroll
    for (int rr = 0; rr < 16; rr++) {
        int row = w * 16 + rr;
        float v[4], sum = 0.0f, sq = 0.0f;
        #pragma unroll
        for (int c = 0; c < 4; c++) {
            v[c] = As[c*STG + row*SMS + lane];
            sum += v[c]; sq += v[c]*v[c];
        }
        #pragma unroll
        for (int o = 16; o > 0; o >>= 1) {
            sum += __shfl_xor_sync(0xffffffffu, sum, o);
            sq  += __shfl_xor_sync(0xffffffffu, sq,  o);
        }
        float mean = sum * (1.0f/128.0f);
        float var  = sq  * (1.0f/128.0f) - mean * mean;
        float r = rsqrtf(var + 1e-5f);
        #pragma unroll
        for (int c = 0; c < 4; c++)
            As[c*STG + row*SMS + lane] = tf32r((v[c] - mean) * r * sc[c] + bc[c]);
    }
}

// ---------------- feature build + grid index (outputs tf32-rounded) ----------------
__global__ void feat_kernel(const float* __restrict__ x) {
    int i = blockIdx.x * blockDim.x + threadIdx.x;
    if (i >= NP) return;
    const float* xr = x + (size_t)i * 24;
    float lat = xr[0];
    if (lat == -90.0f) lat += 0.0001f;
    float lon = xr[1];
    float t   = xr[2];

    int lati = (int)floorf(90.0f - lat);
    int loni = (int)fmodf(180.0f + floorf(lon + 180.0f), 360.0f);
    g_flat[i] = lati * GW + loni;

    float* f = g_feat + (size_t)i * 80;
    f[0] = tf32r(lat * (1.0f/90.0f));
    f[1] = tf32r(lon * (1.0f/180.0f));
    f[2] = tf32r(t   * (1.0f/12.0f));
    #pragma unroll
    for (int j = 3; j < 24; j++) f[j] = tf32r(xr[j]);

    float p0 = -lat - floorf(-lat);
    float p1 =  lon - floorf(lon);
    float p2 =  t + 1.0f;
    f[24] = tf32r(p0); f[25] = tf32r(p1); f[26] = tf32r(p2);
    float p[3] = {p0, p1, p2};
    #pragma unroll
    for (int c = 0; c < 3; c++) {
        float fr = 3.14159274101257324f;
        #pragma unroll
        for (int k = 0; k < 8; k++) {
            float ang = p[c] * fr;
            f[27 + c*8 + k] = tf32r(sinf(ang));
            f[51 + c*8 + k] = tf32r(cosf(ang));
            fr *= 2.0f;
        }
    }
    f[75] = 0.0f; f[76] = 0.0f; f[77] = 0.0f; f[78] = 0.0f; f[79] = 0.0f;
}

// ---------------- all-in-one weight transpose + tf32 round ----------------
__global__ void wconv(const float* __restrict__ W_emb, const float* __restrict__ Wqkv,
                      const float* __restrict__ Wo, const float* __restrict__ Wf1,
                      const float* __restrict__ Wf2, const float* __restrict__ W_comb) {
    int idx = blockIdx.x * blockDim.x + threadIdx.x;
    if (idx >= 696320) return;
    const float* srcs[6] = {W_emb, Wqkv, Wo, Wf1, Wf2, W_comb};
    const int sel [10] = {0,1,1,2,2,3,3,4,4,5};
    const int soff[10] = {0,0,49152,0,16384,0,65536,0,65536,0};
    const int Kt  [10] = {75,128,128,128,128,128,128,512,512,512};
    const int Nt  [10] = {512,384,384,128,128,512,512,128,128,512};
    const int Kp  [10] = {80,128,128,128,128,128,128,512,512,512};
    const int dst [10] = {0,40960,90112,139264,155648,172032,237568,303104,368640,434176};
    int m = 0;
    #pragma unroll
    for (int i = 1; i < 10; i++) if (idx >= dst[i]) m = i;
    int local = idx - dst[m];
    int n = local / Kp[m];
    int k = local - n * Kp[m];
    float v = (k < Kt[m]) ? srcs[sel[m]][soff[m] + (size_t)k * Nt[m] + n] : 0.0f;
    g_wt[idx] = tf32r(v);
}

// ---------------- generic 2-stage GEMM (emb K=80, head K=512) ----------------
template<int EPI, bool CVT>
__global__ void __launch_bounds__(256, 2)
gemm_tc(const float* __restrict__ A, const float* __restrict__ Bt,
        const float* __restrict__ bias, const float* __restrict__ R,
        float* __restrict__ C, int M, int N, int K, int lda, int ldb) {
    extern __shared__ float sm[];
    const int tid  = threadIdx.x;
    const int lane = tid & 31;
    const int w    = tid >> 5;
    const int wm   = w & 3;
    const int wn   = w >> 2;
    const int bm   = blockIdx.y * 128;
    const int bn   = blockIdx.x * 128;

    const uint32_t sA = (uint32_t)__cvta_generic_to_shared(sm);
    const uint32_t sB = sA + 2*STG*4;

    float acc[2][8][4];
    #pragma unroll
    for (int mi = 0; mi < 2; mi++)
        #pragma unroll
        for (int ni = 0; ni < 8; ni++)
            #pragma unroll
            for (int r = 0; r < 4; r++) acc[mi][ni][r] = 0.0f;

    const int lrow = (lane & 7) + ((lane >> 3) & 1) * 8;
    const int lkof = ((lane >> 4) & 1) * 4;
    const int ra0  = wm * 32 + lrow;
    const int rb0  = wn * 64 + lrow;
    const int niter = (K + 31) >> 5;

    auto load_stage = [&](int s, int k0) {
        #pragma unroll
        for (int l = 0; l < 4; l++) {
            int c   = tid + l * 256;
            int row = c >> 3;
            int kc  = (c & 7) << 2;
            bool pa = (bm + row < M) && (k0 + kc < K);
            const float* srcA = pa ? (A + (size_t)(bm + row) * lda + k0 + kc) : A;
            cpasync16(sA + (uint32_t)((s * STG + row * SMS + kc) * 4), srcA, pa);
        }
        #pragma unroll
        for (int l = 0; l < 4; l++) {
            int c   = tid + l * 256;
            int row = c >> 3;
            int kc  = (c & 7) << 2;
            bool pb = (k0 + kc < K);
            const float* srcB = pb ? (Bt + (size_t)(bn + row) * ldb + k0 + kc) : Bt;
            cpasync16(sB + (uint32_t)((s * STG + row * SMS + kc) * 4), srcB, pb);
        }
        cp_commit();
    };

    load_stage(0, 0);
    for (int it = 0; it < niter; it++) {
        if (it + 1 < niter) {
            load_stage((it + 1) & 1, (it + 1) * 32);
            asm volatile("cp.async.wait_group 1;\n" ::);
        } else {
            asm volatile("cp.async.wait_group 0;\n" ::);
        }
        __syncthreads();
        const int s = it & 1;
        mma_tile_128<CVT>(sA + (uint32_t)(s*STG*4), sB + (uint32_t)(s*STG*4), ra0, rb0, lkof, acc);
        __syncthreads();
    }
    epi128<EPI>(acc, bias, R, C, M, N, bm, bn, wm, wn, lane);
}

// ---------------- fused LN + GEMM (QKV): K=128, A=h LayerNormed in smem ----------------
// smem: A full [4][128][36] + B double-buffer [2][128][36] = 110592B
__global__ void __launch_bounds__(256, 2)
gemm_lnqkv(const float* __restrict__ H, const float* __restrict__ Bt,
           const float* __restrict__ bias, const float* __restrict__ lns,
           const float* __restrict__ lnb, float* __restrict__ C, int M, int N) {
    extern __shared__ float sm[];
    float* As = sm;
    const int tid  = threadIdx.x;
    const int lane = tid & 31;
    const int w    = tid >> 5;
    const int bm   = blockIdx.y * 128;
    const int bn   = blockIdx.x * 128;

    const uint32_t sA = (uint32_t)__cvta_generic_to_shared(sm);
    const uint32_t sB = sA + 4*STG*4;

    // load full A tile (group 0)
    #pragma unroll
    for (int l = 0; l < 16; l++) {
        int idx = tid + l * 256;          // 0..4095
        int row = idx >> 5;
        int pos = idx & 31;
        int chunk = pos >> 3;
        int kin = (pos & 7) << 2;
        bool pa = (bm + row) < M;
        const float* src = pa ? (H + (size_t)(bm + row) * 128 + pos * 4) : H;
        cpasync16(sA + (uint32_t)((chunk*STG + row*SMS + kin) * 4), src, pa);
    }
    cp_commit();
    // load B chunk 0 (group 1)
    #pragma unroll
    for (int l = 0; l < 4; l++) {
        int idx = tid + l * 256;
        int row = idx >> 3;
        int kin = (idx & 7) << 2;
        cpasync16(sB + (uint32_t)((row*SMS + kin) * 4), Bt + (size_t)(bn + row) * 128 + kin, true);
    }
    cp_commit();

    asm volatile("cp.async.wait_group 1;\n" ::);   // A done
    __syncthreads();
    ln_smem(As, lns, lnb, w, lane);
    __syncthreads();

    float acc[2][8][4];
    #pragma unroll
    for (int mi = 0; mi < 2; mi++)
        #pragma unroll
        for (int ni = 0; ni < 8; ni++)
            #pragma unroll
            for (int r = 0; r < 4; r++) acc[mi][ni][r] = 0.0f;

    const int lrow = (lane & 7) + ((lane >> 3) & 1) * 8;
    const int lkof = ((lane >> 4) & 1) * 4;
    const int ra0  = (w & 3) * 32 + lrow;
    const int rb0  = (w >> 2) * 64 + lrow;

    for (int kc = 0; kc < 4; kc++) {
        if (kc < 3) {
            int buf = (kc + 1) & 1;
            #pragma unroll
            for (int l = 0; l < 4; l++) {
                int idx = tid + l * 256;
                int row = idx >> 3;
                int kin = (idx & 7) << 2;
                cpasync16(sB + (uint32_t)((buf*STG + row*SMS + kin) * 4),
                          Bt + (size_t)(bn + row) * 128 + (kc + 1) * 32 + kin, true);
            }
            cp_commit();
            asm volatile("cp.async.wait_group 1;\n" ::);
        } else {
            asm volatile("cp.async.wait_group 0;\n" ::);
        }
        __syncthreads();
        mma_tile_128<false>(sA + (uint32_t)(kc*STG*4), sB + (uint32_t)((kc&1)*STG*4),
                            ra0, rb0, lkof, acc);
        __syncthreads();
    }
    epi128<0>(acc, bias, nullptr, C, M, N, bm, bn, w & 3, w >> 2, lane);
}

// ---------------- fused attention + o-proj (+residual): N=128, K=128 ----------------
// 256 threads = 32 points x 8 heads; attention output written into A smem tile.
__global__ void __launch_bounds__(256, 2)
gemm_attn(const float* __restrict__ qkv, const float* __restrict__ Bt,
          const float* __restrict__ bias, float* __restrict__ H, int M) {
    extern __shared__ float sm[];
    float* As = sm;
    const int tid  = threadIdx.x;
    const int lane = tid & 31;
    const int w    = tid >> 5;
    const int bm   = blockIdx.y * 128;

    const uint32_t sA = (uint32_t)__cvta_generic_to_shared(sm);
    const uint32_t sB = sA + 4*STG*4;

    // B chunk 0 (group 0)
    #pragma unroll
    for (int l = 0; l < 4; l++) {
        int idx = tid + l * 256;
        int row = idx >> 3;
        int kin = (idx & 7) << 2;
        cpasync16(sB + (uint32_t)((row*SMS + kin) * 4), Bt + (size_t)row * 128 + kin, true);
    }
    cp_commit();

    // attention: this thread owns (point, head)
    {
        int p_local = tid >> 3;
        int hh = tid & 7;
        int p = (bm >> 2) + p_local;
        if (p < NP) {
            const float* base = qkv + (size_t)p * 1536 + hh * 16;
            #pragma unroll
            for (int qi = 0; qi < 4; qi++) {
                float q[16];
                const float4* qp = (const float4*)(base + qi * 384);
                #pragma unroll
                for (int c = 0; c < 4; c++) {
                    float4 t = qp[c];
                    q[c*4+0] = t.x; q[c*4+1] = t.y; q[c*4+2] = t.z; q[c*4+3] = t.w;
                }
                float sc[4];
                float mx = -1e30f;
                #pragma unroll
                for (int ki = 0; ki < 4; ki++) {
                    const float4* kp = (const float4*)(base + 128 + ki * 384);
                    float s = 0.0f;
                    #pragma unroll
                    for (int c = 0; c < 4; c++) {
                        float4 t = kp[c];
                        s += q[c*4+0]*t.x + q[c*4+1]*t.y + q[c*4+2]*t.z + q[c*4+3]*t.w;
                    }
                    s *= 0.25f;
                    sc[ki] = s;
                    mx = fmaxf(mx, s);
                }
                float sum = 0.0f;
                #pragma unroll
                for (int ki = 0; ki < 4; ki++) { sc[ki] = expf(sc[ki] - mx); sum += sc[ki]; }
                float inv = 1.0f / sum;
                float acco[16];
                #pragma unroll
                for (int d = 0; d < 16; d++) acco[d] = 0.0f;
                #pragma unroll
                for (int ki = 0; ki < 4; ki++) {
                    float wv = sc[ki] * inv;
                    const float4* vp = (const float4*)(base + 256 + ki * 384);
                    #pragma unroll
                    for (int c = 0; c < 4; c++) {
                        float4 t = vp[c];
                        acco[c*4+0] += wv * t.x; acco[c*4+1] += wv * t.y;
                        acco[c*4+2] += wv * t.z; acco[c*4+3] += wv * t.w;
                    }
                }
                int row = p_local * 4 + qi;
                int chunk = hh >> 1;
                int kin = (hh & 1) * 16;
                float* dst = As + chunk*STG + row*SMS + kin;
                #pragma unroll
                for (int c = 0; c < 4; c++) {
                    float4 t;
                    t.x = tf32r(acco[c*4+0]); t.y = tf32r(acco[c*4+1]);
                    t.z = tf32r(acco[c*4+2]); t.w = tf32r(acco[c*4+3]);
                    *(float4*)(dst + c*4) = t;
                }
            }
        } else {
            int p_l = tid >> 3, hh2 = tid & 7;
            #pragma unroll
            for (int qi = 0; qi < 4; qi++) {
                int row = p_l * 4 + qi;
                float* dst = As + (hh2>>1)*STG + row*SMS + (hh2&1)*16;
                #pragma unroll
                for (int c = 0; c < 4; c++) *(float4*)(dst + c*4) = make_float4(0,0,0,0);
            }
        }
    }

    float acc[2][8][4];
    #pragma unroll
    for (int mi = 0; mi < 2; mi++)
        #pragma unroll
        for (int ni = 0; ni < 8; ni++)
            #pragma unroll
            for (int r = 0; r < 4; r++) acc[mi][ni][r] = 0.0f;

    const int lrow = (lane & 7) + ((lane >> 3) & 1) * 8;
    const int lkof = ((lane >> 4) & 1) * 4;
    const int ra0  = (w & 3) * 32 + lrow;
    const int rb0  = (w >> 2) * 64 + lrow;

    for (int kc = 0; kc < 4; kc++) {
        if (kc < 3) {
            int buf = (kc + 1) & 1;
            #pragma unroll
            for (int l = 0; l < 4; l++) {
                int idx = tid + l * 256;
                int row = idx >> 3;
                int kin = (idx & 7) << 2;
                cpasync16(sB + (uint32_t)((buf*STG + row*SMS + kin) * 4),
                          Bt + (size_t)row * 128 + (kc + 1) * 32 + kin, true);
            }
            cp_commit();
            asm volatile("cp.async.wait_group 1;\n" ::);
        } else {
            asm volatile("cp.async.wait_group 0;\n" ::);
        }
        __syncthreads();
        mma_tile_128<false>(sA + (uint32_t)(kc*STG*4), sB + (uint32_t)((kc&1)*STG*4),
                            ra0, rb0, lkof, acc);
        __syncthreads();
    }
    epi128<1>(acc, bias, H, H, M, 128, bm, 0, w & 3, w >> 2, lane);
}

// ---------------- fused LN2 + FF1 + GELU + FF2 (+residual) ----------------
// smem (floats): a [4][128][36]=18432 | B1 2x4608 | G [128][36]=4608 | B2 2x4608 -> 41472 fl = 165888 B
__global__ void __launch_bounds__(256, 1)
gemm_ffn(float* __restrict__ H, const float* __restrict__ B1t,
         const float* __restrict__ B2t, const float* __restrict__ bf1,
         const float* __restrict__ bf2, const float* __restrict__ lns,
         const float* __restrict__ lnb, int M) {
    extern __shared__ float sm[];
    float* As = sm;                 // 18432
    float* Gp = sm + 27648;         // 4608
    const int tid  = threadIdx.x;
    const int lane = tid & 31;
    const int w    = tid >> 5;
    const int bm   = blockIdx.y * 128;

    const uint32_t sA  = (uint32_t)__cvta_generic_to_shared(sm);
    const uint32_t sB1 = sA + 18432u*4;
    const uint32_t sG  = sA + 27648u*4;
    const uint32_t sB2 = sA + 32256u*4;

    // load a = h tile (group 0)
    #pragma unroll
    for (int l = 0; l < 16; l++) {
        int idx = tid + l * 256;
        int row = idx >> 5;
        int pos = idx & 31;
        int chunk = pos >> 3;
        int kin = (pos & 7) << 2;
        bool pa = (bm + row) < M;
        const float* src = pa ? (H + (size_t)(bm + row) * 128 + pos * 4) : H;
        cpasync16(sA + (uint32_t)((chunk*STG + row*SMS + kin) * 4), src, pa);
    }
    cp_commit();

    // prefetch B1[0], B2[0] (group 1)
    #pragma unroll
    for (int l = 0; l < 4; l++) {
        int idx = tid + l * 256;
        { // B1 sub: [4kc][32][36]
            int row = idx >> 5;
            int pos = idx & 31;
            int chunk = pos >> 3;
            int kin = (pos & 7) << 2;
            cpasync16(sB1 + (uint32_t)((chunk*1152 + row*SMS + kin) * 4),
                      B1t + (size_t)row * 128 + pos * 4, true);
        }
        { // B2 sub: [128][36]
            int row = idx >> 3;
            int kin = (idx & 7) << 2;
            cpasync16(sB2 + (uint32_t)((row*SMS + kin) * 4),
                      B2t + (size_t)row * 512 + kin, true);
        }
    }
    cp_commit();

    asm volatile("cp.async.wait_group 1;\n" ::);   // a done
    __syncthreads();
    ln_smem(As, lns, lnb, w, lane);
    __syncthreads();

    const int lrow = (lane & 7) + ((lane >> 3) & 1) * 8;
    const int lkof = ((lane >> 4) & 1) * 4;
    const int ra1  = w * 16 + lrow;               // FF1: warp tile 16 rows
    const int ra2  = (w & 3) * 32 + lrow;         // FF2
    const int rb2  = (w >> 2) * 64 + lrow;

    float acc2[2][8][4];
    #pragma unroll
    for (int mi = 0; mi < 2; mi++)
        #pragma unroll
        for (int ni = 0; ni < 8; ni++)
            #pragma unroll
            for (int r = 0; r < 4; r++) acc2[mi][ni][r] = 0.0f;

    for (int nsub = 0; nsub < 16; nsub++) {
        const int buf = nsub & 1;
        if (nsub < 15) {
            const int nbuf = (nsub + 1) & 1;
            #pragma unroll
            for (int l = 0; l < 4; l++) {
                int idx = tid + l * 256;
                {
                    int row = idx >> 5;
                    int pos = idx & 31;
                    int chunk = pos >> 3;
                    int kin = (pos & 7) << 2;
                    cpasync16(sB1 + (uint32_t)((nbuf*4608 + chunk*1152 + row*SMS + kin) * 4),
                              B1t + (size_t)((nsub + 1) * 32 + row) * 128 + pos * 4, true);
                }
                {
                    int row = idx >> 3;
                    int kin = (idx & 7) << 2;
                    cpasync16(sB2 + (uint32_t)((nbuf*4608 + row*SMS + kin) * 4),
                              B2t + (size_t)row * 512 + (nsub + 1) * 32 + kin, true);
                }
            }
            cp_commit();
            asm volatile("cp.async.wait_group 1;\n" ::);
        } else {
            asm volatile("cp.async.wait_group 0;\n" ::);
        }
        __syncthreads();   // B bufs ready; prev-iter G reads complete

        // FF1: 128x32 output sub-tile, warp tile 16x32
        float acc1[4][4];
        #pragma unroll
        for (int nf = 0; nf < 4; nf++)
            #pragma unroll
            for (int r = 0; r < 4; r++) acc1[nf][r] = 0.0f;

        #pragma unroll
        for (int kc = 0; kc < 4; kc++) {
            uint32_t aB = sA + (uint32_t)(kc*STG*4);
            uint32_t bB = sB1 + (uint32_t)((buf*4608 + kc*1152) * 4);
            #pragma unroll
            for (int kk = 0; kk < 32; kk += 8) {
                uint32_t a4[4];
                ldm4(a4[0], a4[1], a4[2], a4[3],
                     aB + (uint32_t)((ra1*SMS + kk + lkof) * 4));
                uint32_t b0[4], b1r[4];
                #pragma unroll
                for (int np = 0; np < 2; np++) {
                    uint32_t r0, r1, r2, r3;
                    ldm4(r0, r1, r2, r3,
                         bB + (uint32_t)(((np*16 + lrow)*SMS + kk + lkof) * 4));
                    b0[2*np] = r0; b0[2*np+1] = r1;
                    b1r[2*np] = r2; b1r[2*np+1] = r3;
                }
                #pragma unroll
                for (int nf = 0; nf < 4; nf++)
                    mma_tf32(acc1[nf], a4, b0[nf], b1r[nf]);
            }
        }

        // gelu + bias -> G (tf32-rounded)
        {
            int r0 = w * 16 + (lane >> 2);
            int c0 = (lane & 3) * 2;
            #pragma unroll
            for (int nf = 0; nf < 4; nf++) {
                #pragma unroll
                for (int half = 0; half < 2; half++) {
                    int row = r0 + half * 8;
                    int col = nf * 8 + c0;
                    int gcol = nsub * 32 + col;
                    float v0 = tf32r(gelu_t(acc1[nf][half*2 + 0] + bf1[gcol]));
                    float v1 = tf32r(gelu_t(acc1[nf][half*2 + 1] + bf1[gcol + 1]));
                    float2 o; o.x = v0; o.y = v1;
                    *(float2*)(Gp + row*SMS + col) = o;
                }
            }
        }
        __syncthreads();   // G visible

        // FF2: accumulate G (128x32) @ B2sub into acc2
        mma_tile_128<false>(sG, sB2 + (uint32_t)(buf*4608*4), ra2, rb2, lkof, acc2);
        __syncthreads();   // all reads of B bufs + G done before next-iter overwrite
    }

    epi128<1>(acc2, bf2, H, H, M, 128, bm, 0, w & 3, w >> 2, lane);
}

// ---------------- segment mean ----------------
__global__ void zero_kernel(float* __restrict__ out) {
    int i = blockIdx.x * blockDim.x + threadIdx.x;
    if (i < NCELL * CLN) out[i] = 0.0f;
    else if (i < NCELL * CLN + NCELL) g_cnt[i - NCELL * CLN] = 0.0f;
}

__global__ void scatter_kernel(float* __restrict__ out) {
    int idx = blockIdx.x * blockDim.x + threadIdx.x;
    if (idx >= NP * 512) return;
    int n = idx >> 9;
    int j = idx & 511;
    int cell = g_flat[n];
    atomicAdd(out + (size_t)cell * 512 + j, g_y[idx]);
    if (j == 0) atomicAdd(&g_cnt[cell], 1.0f);
}

__global__ void div_kernel(float* __restrict__ out) {
    int i = blockIdx.x * blockDim.x + threadIdx.x;
    if (i >= NCELL * 512) return;
    out[i] *= 1.0f / fmaxf(g_cnt[i >> 9], 1.0f);
}

// ---------------- driver ----------------
extern "C" void kernel_launch(void* const* d_in, const int* in_sizes, int n_in,
                              void* d_out, int out_size) {
    const float* x      = (const float*)d_in[0];
    const float* W_emb  = (const float*)d_in[1];
    const float* b_emb  = (const float*)d_in[2];
    const float* ln1_s  = (const float*)d_in[3];
    const float* ln1_b  = (const float*)d_in[4];
    const float* Wqkv   = (const float*)d_in[5];
    const float* bqkv   = (const float*)d_in[6];
    const float* Wo     = (const float*)d_in[7];
    const float* bo     = (const float*)d_in[8];
    const float* ln2_s  = (const float*)d_in[9];
    const float* ln2_b  = (const float*)d_in[10];
    const float* Wf1    = (const float*)d_in[11];
    const float* bf1    = (const float*)d_in[12];
    const float* Wf2    = (const float*)d_in[13];
    const float* bf2    = (const float*)d_in[14];
    const float* W_comb = (const float*)d_in[15];
    const float* b_comb = (const float*)d_in[16];
    float* out = (float*)d_out;

    float *p_feat, *p_h, *p_qkv, *p_y, *p_wt;
    cudaGetSymbolAddress((void**)&p_feat, g_feat);
    cudaGetSymbolAddress((void**)&p_h,    g_h);
    cudaGetSymbolAddress((void**)&p_qkv,  g_qkv);
    cudaGetSymbolAddress((void**)&p_y,    g_y);
    cudaGetSymbolAddress((void**)&p_wt,   g_wt);

    const int SMEM_G  = 73728;    // generic
    const int SMEM_Q  = 110592;   // lnqkv / attn
    const int SMEM_F  = 165888;   // ffn
    static bool attr_done = false;
    if (!attr_done) {
        cudaFuncSetAttribute((const void*)gemm_tc<0,false>, cudaFuncAttributeMaxDynamicSharedMemorySize, SMEM_G);
        cudaFuncSetAttribute((const void*)gemm_tc<0,true>,  cudaFuncAttributeMaxDynamicSharedMemorySize, SMEM_G);
        cudaFuncSetAttribute((const void*)gemm_lnqkv, cudaFuncAttributeMaxDynamicSharedMemorySize, SMEM_Q);
        cudaFuncSetAttribute((const void*)gemm_attn,  cudaFuncAttributeMaxDynamicSharedMemorySize, SMEM_Q);
        cudaFuncSetAttribute((const void*)gemm_ffn,   cudaFuncAttributeMaxDynamicSharedMemorySize, SMEM_F);
        attr_done = true;
    }

    const int TB = 256;

    // weight offsets (floats) in g_wt
    float* wembT  = p_wt + 0;
    float* wqkvT0 = p_wt + 40960;
    float* wqkvT1 = p_wt + 90112;
    float* woT0   = p_wt + 139264;
    float* woT1   = p_wt + 155648;
    float* wf1T0  = p_wt + 172032;
    float* wf1T1  = p_wt + 237568;
    float* wf2T0  = p_wt + 303104;
    float* wf2T1  = p_wt + 368640;
    float* wcombT = p_wt + 434176;

    wconv<<<(696320 + TB - 1) / TB, TB>>>(W_emb, Wqkv, Wo, Wf1, Wf2, W_comb);
    feat_kernel<<<(NP + TB - 1) / TB, TB>>>(x);

    // embedding
    gemm_tc<0,false><<<dim3(4, (NP + 127) / 128), TB, SMEM_G>>>(
        p_feat, wembT, b_emb, nullptr, p_h, NP, 512, 80, 80, 80);

    const float* wqkvT[2] = {wqkvT0, wqkvT1};
    const float* woT[2]   = {woT0, woT1};
    const float* wf1T[2]  = {wf1T0, wf1T1};
    const float* wf2T[2]  = {wf2T0, wf2T1};
    const int MB = (NTOK + 127) / 128;   // 2048

    for (int i = 0; i < 2; i++) {
        gemm_lnqkv<<<dim3(3, MB), TB, SMEM_Q>>>(p_h, wqkvT[i], bqkv + i * 384,
                                                ln1_s + i * 128, ln1_b + i * 128,
                                                p_qkv, NTOK, 384);
        gemm_attn<<<dim3(1, MB), TB, SMEM_Q>>>(p_qkv, woT[i], bo + i * 128, p_h, NTOK);
        gemm_ffn<<<dim3(1, MB), TB, SMEM_F>>>(p_h, wf1T[i], wf2T[i],
                                              bf1 + i * 512, bf2 + i * 128,
                                              ln2_s + i * 128, ln2_b + i * 128, NTOK);
    }

    // head
    gemm_tc<0,true><<<dim3(4, (NP + 127) / 128), TB, SMEM_G>>>(
        p_h, wcombT, b_comb, nullptr, p_y, NP, 512, 512, 512, 512);

    // segment mean
    zero_kernel<<<(NCELL * CLN + NCELL + TB - 1) / TB, TB>>>(out);
    scatter_kernel<<<(NP * 512 + TB - 1) / TB, TB>>>(out);
    div_kernel<<<(NCELL * 512 + TB - 1) / TB, TB>>>(out);
}

// round 7
// speedup vs baseline: 1.0677x; 1.0677x over previous
#include <cuda_runtime.h>
#include <math.h>
#include <stdint.h>

#define NP    65534
#define NTOK  (NP*4)          // 262136 tokens
#define GH    180
#define GW    360
#define NCELL (GH*GW)         // 64800
#define CLN   512

// ---------------- scratch (device globals: no allocation allowed) ----------------
__device__ float g_feat[(size_t)NP*80];      // 75 used + zero pad to 80 (tf32-rounded)
__device__ int   g_flat[NP];
__device__ float g_h   [(size_t)NTOK*128];   // transformer state (fp32)
__device__ float g_qkv [(size_t)NTOK*384];
__device__ float g_gel [(size_t)NTOK*512];   // gelu output (tf32-rounded)
__device__ float g_y   [(size_t)NP*512];
__device__ float g_cnt [NCELL];
__device__ float g_wt  [696320];             // transposed, tf32-rounded weights

// ---------------- small PTX helpers ----------------
__device__ __forceinline__ uint32_t f2tf32(float x) {
    uint32_t r;
    asm("cvt.rna.tf32.f32 %0, %1;" : "=r"(r) : "f"(x));
    return r;
}
__device__ __forceinline__ float tf32r(float x) { return __uint_as_float(f2tf32(x)); }

__device__ __forceinline__ void cpasync16(uint32_t dst, const float* src, bool pred) {
    int sz = pred ? 16 : 0;      // sz=0 => zero-fill 16 bytes
    asm volatile("cp.async.cg.shared.global [%0], [%1], 16, %2;\n"
                 :: "r"(dst), "l"(src), "r"(sz));
}
__device__ __forceinline__ void cp_commit() {
    asm volatile("cp.async.commit_group;\n" ::);
}
__device__ __forceinline__ void ldm4(uint32_t& r0, uint32_t& r1, uint32_t& r2, uint32_t& r3, uint32_t addr) {
    asm volatile("ldmatrix.sync.aligned.m8n8.x4.shared.b16 {%0,%1,%2,%3}, [%4];\n"
                 : "=r"(r0), "=r"(r1), "=r"(r2), "=r"(r3) : "r"(addr));
}
__device__ __forceinline__ void mma_tf32(float* c, const uint32_t* a, uint32_t b0, uint32_t b1) {
    asm volatile("mma.sync.aligned.m16n8k8.row.col.f32.tf32.tf32.f32 "
                 "{%0,%1,%2,%3}, {%4,%5,%6,%7}, {%8,%9}, {%0,%1,%2,%3};\n"
                 : "+f"(c[0]), "+f"(c[1]), "+f"(c[2]), "+f"(c[3])
                 : "r"(a[0]), "r"(a[1]), "r"(a[2]), "r"(a[3]), "r"(b0), "r"(b1));
}
__device__ __forceinline__ float gelu_t(float u) {
    return 0.5f * u * (1.0f + tanhf(0.7978845608028654f * (u + 0.044715f * u * u * u)));
}

#define SMS 36
#define STG (128*SMS)   // 4608 floats = one 128x32 chunk

// 128x128x32 mma on one k-chunk: aBase/bBase = smem byte addr of [128][36] chunk
template<bool CVT>
__device__ __forceinline__ void mma_tile_128(uint32_t aBase, uint32_t bBase,
                                             int ra0, int rb0, int lkof,
                                             float acc[2][8][4]) {
    #pragma unroll
    for (int kk = 0; kk < 32; kk += 8) {
        uint32_t a[2][4];
        #pragma unroll
        for (int mi = 0; mi < 2; mi++) {
            ldm4(a[mi][0], a[mi][1], a[mi][2], a[mi][3],
                 aBase + (uint32_t)(((ra0 + mi * 16) * SMS + kk + lkof) * 4));
            if (CVT) {
                #pragma unroll
                for (int r = 0; r < 4; r++) a[mi][r] = f2tf32(__uint_as_float(a[mi][r]));
            }
        }
        uint32_t b0[8], b1[8];
        #pragma unroll
        for (int np = 0; np < 4; np++) {
            uint32_t r0, r1, r2, r3;
            ldm4(r0, r1, r2, r3, bBase + (uint32_t)(((rb0 + np * 16) * SMS + kk + lkof) * 4));
            b0[2*np] = r0; b0[2*np+1] = r1;
            b1[2*np] = r2; b1[2*np+1] = r3;
        }
        #pragma unroll
        for (int mi = 0; mi < 2; mi++)
            #pragma unroll
            for (int ni = 0; ni < 8; ni++)
                mma_tf32(acc[mi][ni], a[mi], b0[ni], b1[ni]);
    }
}

// shared epilogue for 128-row tiles, warp layout 4x2 (warp tile 32x64)
template<int EPI>   // 0=bias, 1=bias+residual, 2=bias+gelu(tf32r)
__device__ __forceinline__ void epi128(float acc[2][8][4], const float* __restrict__ bias,
                                       const float* __restrict__ R, float* __restrict__ C,
                                       int M, int N, int bm, int bn, int wm, int wn, int lane) {
    const int row0 = bm + wm * 32 + (lane >> 2);
    const int col0 = bn + wn * 64 + (lane & 3) * 2;
    #pragma unroll
    for (int mi = 0; mi < 2; mi++) {
        #pragma unroll
        for (int half = 0; half < 2; half++) {
            int gm = row0 + mi * 16 + half * 8;
            if (gm >= M) continue;
            #pragma unroll
            for (int ni = 0; ni < 8; ni++) {
                int gn = col0 + ni * 8;
                float v0 = acc[mi][ni][half*2 + 0] + bias[gn];
                float v1 = acc[mi][ni][half*2 + 1] + bias[gn + 1];
                if (EPI == 1) {
                    const float2 rr = *(const float2*)(R + (size_t)gm * N + gn);
                    v0 += rr.x; v1 += rr.y;
                }
                if (EPI == 2) { v0 = tf32r(gelu_t(v0)); v1 = tf32r(gelu_t(v1)); }
                float2 o; o.x = v0; o.y = v1;
                *(float2*)(C + (size_t)gm * N + gn) = o;
            }
        }
    }
}

// LayerNorm the 128x128 A tile in smem (4 chunks of [128][36]); output tf32-rounded
__device__ __forceinline__ void ln_smem(float* As, const float* __restrict__ s,
                                        const float* __restrict__ b, int w, int lane) {
    float sc[4], bc[4];
    #pragma unroll
    for (int c = 0; c < 4; c++) { sc[c] = s[c*32 + lane]; bc[c] = b[c*32 + lane]; }
    #pragma unroll
    for (int rr = 0; rr < 16; rr++) {
        int row = w * 16 + rr;
        float v[4], sum = 0.0f, sq = 0.0f;
        #pragma unroll
        for (int c = 0; c < 4; c++) {
            v[c] = As[c*STG + row*SMS + lane];
            sum += v[c]; sq += v[c]*v[c];
        }
        #pragma unroll
        for (int o = 16; o > 0; o >>= 1) {
            sum += __shfl_xor_sync(0xffffffffu, sum, o);
            sq  += __shfl_xor_sync(0xffffffffu, sq,  o);
        }
        float mean = sum * (1.0f/128.0f);
        float var  = sq  * (1.0f/128.0f) - mean * mean;
        float r = rsqrtf(var + 1e-5f);
        #pragma unroll
        for (int c = 0; c < 4; c++)
            As[c*STG + row*SMS + lane] = tf32r((v[c] - mean) * r * sc[c] + bc[c]);
    }
}

// ---------------- feature build + grid index (outputs tf32-rounded) ----------------
__global__ void feat_kernel(const float* __restrict__ x) {
    int i = blockIdx.x * blockDim.x + threadIdx.x;
    if (i >= NP) return;
    const float* xr = x + (size_t)i * 24;
    float lat = xr[0];
    if (lat == -90.0f) lat += 0.0001f;
    float lon = xr[1];
    float t   = xr[2];

    int lati = (int)floorf(90.0f - lat);
    int loni = (int)fmodf(180.0f + floorf(lon + 180.0f), 360.0f);
    g_flat[i] = lati * GW + loni;

    float* f = g_feat + (size_t)i * 80;
    f[0] = tf32r(lat * (1.0f/90.0f));
    f[1] = tf32r(lon * (1.0f/180.0f));
    f[2] = tf32r(t   * (1.0f/12.0f));
    #pragma unroll
    for (int j = 3; j < 24; j++) f[j] = tf32r(xr[j]);

    float p0 = -lat - floorf(-lat);
    float p1 =  lon - floorf(lon);
    float p2 =  t + 1.0f;
    f[24] = tf32r(p0); f[25] = tf32r(p1); f[26] = tf32r(p2);
    float p[3] = {p0, p1, p2};
    #pragma unroll
    for (int c = 0; c < 3; c++) {
        float fr = 3.14159274101257324f;
        #pragma unroll
        for (int k = 0; k < 8; k++) {
            float ang = p[c] * fr;
            f[27 + c*8 + k] = tf32r(sinf(ang));
            f[51 + c*8 + k] = tf32r(cosf(ang));
            fr *= 2.0f;
        }
    }
    f[75] = 0.0f; f[76] = 0.0f; f[77] = 0.0f; f[78] = 0.0f; f[79] = 0.0f;
}

// ---------------- all-in-one weight transpose + tf32 round ----------------
__global__ void wconv(const float* __restrict__ W_emb, const float* __restrict__ Wqkv,
                      const float* __restrict__ Wo, const float* __restrict__ Wf1,
                      const float* __restrict__ Wf2, const float* __restrict__ W_comb) {
    int idx = blockIdx.x * blockDim.x + threadIdx.x;
    if (idx >= 696320) return;
    const float* srcs[6] = {W_emb, Wqkv, Wo, Wf1, Wf2, W_comb};
    const int sel [10] = {0,1,1,2,2,3,3,4,4,5};
    const int soff[10] = {0,0,49152,0,16384,0,65536,0,65536,0};
    const int Kt  [10] = {75,128,128,128,128,128,128,512,512,512};
    const int Nt  [10] = {512,384,384,128,128,512,512,128,128,512};
    const int Kp  [10] = {80,128,128,128,128,128,128,512,512,512};
    const int dst [10] = {0,40960,90112,139264,155648,172032,237568,303104,368640,434176};
    int m = 0;
    #pragma unroll
    for (int i = 1; i < 10; i++) if (idx >= dst[i]) m = i;
    int local = idx - dst[m];
    int n = local / Kp[m];
    int k = local - n * Kp[m];
    float v = (k < Kt[m]) ? srcs[sel[m]][soff[m] + (size_t)k * Nt[m] + n] : 0.0f;
    g_wt[idx] = tf32r(v);
}

// ---------------- generic 2-stage GEMM (emb K=80, ff2 K=512, head K=512) ----------------
template<int EPI, bool CVT>
__global__ void __launch_bounds__(256, 2)
gemm_tc(const float* __restrict__ A, const float* __restrict__ Bt,
        const float* __restrict__ bias, const float* __restrict__ R,
        float* __restrict__ C, int M, int N, int K, int lda, int ldb) {
    extern __shared__ float sm[];
    const int tid  = threadIdx.x;
    const int lane = tid & 31;
    const int w    = tid >> 5;
    const int wm   = w & 3;
    const int wn   = w >> 2;
    const int bm   = blockIdx.y * 128;
    const int bn   = blockIdx.x * 128;

    const uint32_t sA = (uint32_t)__cvta_generic_to_shared(sm);
    const uint32_t sB = sA + 2*STG*4;

    float acc[2][8][4];
    #pragma unroll
    for (int mi = 0; mi < 2; mi++)
        #pragma unroll
        for (int ni = 0; ni < 8; ni++)
            #pragma unroll
            for (int r = 0; r < 4; r++) acc[mi][ni][r] = 0.0f;

    const int lrow = (lane & 7) + ((lane >> 3) & 1) * 8;
    const int lkof = ((lane >> 4) & 1) * 4;
    const int ra0  = wm * 32 + lrow;
    const int rb0  = wn * 64 + lrow;
    const int niter = (K + 31) >> 5;

    auto load_stage = [&](int s, int k0) {
        #pragma unroll
        for (int l = 0; l < 4; l++) {
            int c   = tid + l * 256;
            int row = c >> 3;
            int kc  = (c & 7) << 2;
            bool pa = (bm + row < M) && (k0 + kc < K);
            const float* srcA = pa ? (A + (size_t)(bm + row) * lda + k0 + kc) : A;
            cpasync16(sA + (uint32_t)((s * STG + row * SMS + kc) * 4), srcA, pa);
        }
        #pragma unroll
        for (int l = 0; l < 4; l++) {
            int c   = tid + l * 256;
            int row = c >> 3;
            int kc  = (c & 7) << 2;
            bool pb = (k0 + kc < K);
            const float* srcB = pb ? (Bt + (size_t)(bn + row) * ldb + k0 + kc) : Bt;
            cpasync16(sB + (uint32_t)((s * STG + row * SMS + kc) * 4), srcB, pb);
        }
        cp_commit();
    };

    load_stage(0, 0);
    for (int it = 0; it < niter; it++) {
        if (it + 1 < niter) {
            load_stage((it + 1) & 1, (it + 1) * 32);
            asm volatile("cp.async.wait_group 1;\n" ::);
        } else {
            asm volatile("cp.async.wait_group 0;\n" ::);
        }
        __syncthreads();
        const int s = it & 1;
        mma_tile_128<CVT>(sA + (uint32_t)(s*STG*4), sB + (uint32_t)(s*STG*4), ra0, rb0, lkof, acc);
        __syncthreads();
    }
    epi128<EPI>(acc, bias, R, C, M, N, bm, bn, wm, wn, lane);
}

// ---------------- fused LN + GEMM over ALL n-blocks (A resident): K=128 ----------------
// smem: A full [4][128][36] + B double-buffer [2][128][36] = 110592B. grid (1, M/128).
// EPI=0: C=qkv (N=384). EPI=2: C=g_gel with gelu (N=512).
template<int EPI>
__global__ void __launch_bounds__(256, 2)
gemm_lnA(const float* __restrict__ H, const float* __restrict__ Bt,
         const float* __restrict__ bias, const float* __restrict__ lns,
         const float* __restrict__ lnb, float* __restrict__ C, int M, int N) {
    extern __shared__ float sm[];
    float* As = sm;
    const int tid  = threadIdx.x;
    const int lane = tid & 31;
    const int w    = tid >> 5;
    const int bm   = blockIdx.y * 128;

    const uint32_t sA = (uint32_t)__cvta_generic_to_shared(sm);
    const uint32_t sB = sA + 4*STG*4;

    // load full A tile (group 0)
    #pragma unroll
    for (int l = 0; l < 16; l++) {
        int idx = tid + l * 256;          // 0..4095
        int row = idx >> 5;
        int pos = idx & 31;
        int chunk = pos >> 3;
        int kin = (pos & 7) << 2;
        bool pa = (bm + row) < M;
        const float* src = pa ? (H + (size_t)(bm + row) * 128 + pos * 4) : H;
        cpasync16(sA + (uint32_t)((chunk*STG + row*SMS + kin) * 4), src, pa);
    }
    cp_commit();

    // B stage loader: stage s -> n-block s>>2, k-chunk s&3, buffer s&1
    auto loadB = [&](int s) {
        int nb = s >> 2, kc = s & 3, buf = s & 1;
        #pragma unroll
        for (int l = 0; l < 4; l++) {
            int idx = tid + l * 256;
            int row = idx >> 3;
            int kin = (idx & 7) << 2;
            cpasync16(sB + (uint32_t)((buf*STG + row*SMS + kin) * 4),
                      Bt + (size_t)(nb * 128 + row) * 128 + kc * 32 + kin, true);
        }
        cp_commit();
    };

    loadB(0);
    asm volatile("cp.async.wait_group 1;\n" ::);   // A done
    __syncthreads();
    ln_smem(As, lns, lnb, w, lane);
    __syncthreads();

    const int lrow = (lane & 7) + ((lane >> 3) & 1) * 8;
    const int lkof = ((lane >> 4) & 1) * 4;
    const int ra0  = (w & 3) * 32 + lrow;
    const int rb0  = (w >> 2) * 64 + lrow;

    float acc[2][8][4];
    const int nst = (N >> 7) * 4;
    for (int s = 0; s < nst; s++) {
        if (s + 1 < nst) {
            loadB(s + 1);
            asm volatile("cp.async.wait_group 1;\n" ::);
        } else {
            asm volatile("cp.async.wait_group 0;\n" ::);
        }
        __syncthreads();
        if ((s & 3) == 0) {
            #pragma unroll
            for (int mi = 0; mi < 2; mi++)
                #pragma unroll
                for (int ni = 0; ni < 8; ni++)
                    #pragma unroll
                    for (int r = 0; r < 4; r++) acc[mi][ni][r] = 0.0f;
        }
        mma_tile_128<false>(sA + (uint32_t)((s & 3)*STG*4), sB + (uint32_t)((s & 1)*STG*4),
                            ra0, rb0, lkof, acc);
        if ((s & 3) == 3)
            epi128<EPI>(acc, bias, nullptr, C, M, N, bm, (s >> 2) * 128, w & 3, w >> 2, lane);
        __syncthreads();
    }
}

// ---------------- fused attention + o-proj (+residual): N=128, K=128 ----------------
// 256 threads = 32 points x 8 heads; attention output written into A smem tile.
__global__ void __launch_bounds__(256, 2)
gemm_attn(const float* __restrict__ qkv, const float* __restrict__ Bt,
          const float* __restrict__ bias, float* __restrict__ H, int M) {
    extern __shared__ float sm[];
    float* As = sm;
    const int tid  = threadIdx.x;
    const int lane = tid & 31;
    const int w    = tid >> 5;
    const int bm   = blockIdx.y * 128;

    const uint32_t sA = (uint32_t)__cvta_generic_to_shared(sm);
    const uint32_t sB = sA + 4*STG*4;

    // B chunk 0 (group 0)
    #pragma unroll
    for (int l = 0; l < 4; l++) {
        int idx = tid + l * 256;
        int row = idx >> 3;
        int kin = (idx & 7) << 2;
        cpasync16(sB + (uint32_t)((row*SMS + kin) * 4), Bt + (size_t)row * 128 + kin, true);
    }
    cp_commit();

    // attention: this thread owns (point, head)
    {
        int p_local = tid >> 3;
        int hh = tid & 7;
        int p = (bm >> 2) + p_local;
        if (p < NP) {
            const float* base = qkv + (size_t)p * 1536 + hh * 16;
            #pragma unroll
            for (int qi = 0; qi < 4; qi++) {
                float q[16];
                const float4* qp = (const float4*)(base + qi * 384);
                #pragma unroll
                for (int c = 0; c < 4; c++) {
                    float4 t = qp[c];
                    q[c*4+0] = t.x; q[c*4+1] = t.y; q[c*4+2] = t.z; q[c*4+3] = t.w;
                }
                float sc[4];
                float mx = -1e30f;
                #pragma unroll
                for (int ki = 0; ki < 4; ki++) {
                    const float4* kp = (const float4*)(base + 128 + ki * 384);
                    float s = 0.0f;
                    #pragma unroll
                    for (int c = 0; c < 4; c++) {
                        float4 t = kp[c];
                        s += q[c*4+0]*t.x + q[c*4+1]*t.y + q[c*4+2]*t.z + q[c*4+3]*t.w;
                    }
                    s *= 0.25f;
                    sc[ki] = s;
                    mx = fmaxf(mx, s);
                }
                float sum = 0.0f;
                #pragma unroll
                for (int ki = 0; ki < 4; ki++) { sc[ki] = expf(sc[ki] - mx); sum += sc[ki]; }
                float inv = 1.0f / sum;
                float acco[16];
                #pragma unroll
                for (int d = 0; d < 16; d++) acco[d] = 0.0f;
                #pragma unroll
                for (int ki = 0; ki < 4; ki++) {
                    float wv = sc[ki] * inv;
                    const float4* vp = (const float4*)(base + 256 + ki * 384);
                    #pragma unroll
                    for (int c = 0; c < 4; c++) {
                        float4 t = vp[c];
                        acco[c*4+0] += wv * t.x; acco[c*4+1] += wv * t.y;
                        acco[c*4+2] += wv * t.z; acco[c*4+3] += wv * t.w;
                    }
                }
                int row = p_local * 4 + qi;
                int chunk = hh >> 1;
                int kin = (hh & 1) * 16;
                float* dst = As + chunk*STG + row*SMS + kin;
                #pragma unroll
                for (int c = 0; c < 4; c++) {
                    float4 t;
                    t.x = tf32r(acco[c*4+0]); t.y = tf32r(acco[c*4+1]);
                    t.z = tf32r(acco[c*4+2]); t.w = tf32r(acco[c*4+3]);
                    *(float4*)(dst + c*4) = t;
                }
            }
        } else {
            int p_l = tid >> 3, hh2 = tid & 7;
            #pragma unroll
            for (int qi = 0; qi < 4; qi++) {
                int row = p_l * 4 + qi;
                float* dst = As + (hh2>>1)*STG + row*SMS + (hh2&1)*16;
                #pragma unroll
                for (int c = 0; c < 4; c++) *(float4*)(dst + c*4) = make_float4(0,0,0,0);
            }
        }
    }

    float acc[2][8][4];
    #pragma unroll
    for (int mi = 0; mi < 2; mi++)
        #pragma unroll
        for (int ni = 0; ni < 8; ni++)
            #pragma unroll
            for (int r = 0; r < 4; r++) acc[mi][ni][r] = 0.0f;

    const int lrow = (lane & 7) + ((lane >> 3) & 1) * 8;
    const int lkof = ((lane >> 4) & 1) * 4;
    const int ra0  = (w & 3) * 32 + lrow;
    const int rb0  = (w >> 2) * 64 + lrow;

    for (int kc = 0; kc < 4; kc++) {
        if (kc < 3) {
            int buf = (kc + 1) & 1;
            #pragma unroll
            for (int l = 0; l < 4; l++) {
                int idx = tid + l * 256;
                int row = idx >> 3;
                int kin = (idx & 7) << 2;
                cpasync16(sB + (uint32_t)((buf*STG + row*SMS + kin) * 4),
                          Bt + (size_t)row * 128 + (kc + 1) * 32 + kin, true);
            }
            cp_commit();
            asm volatile("cp.async.wait_group 1;\n" ::);
        } else {
            asm volatile("cp.async.wait_group 0;\n" ::);
        }
        __syncthreads();
        mma_tile_128<false>(sA + (uint32_t)(kc*STG*4), sB + (uint32_t)((kc&1)*STG*4),
                            ra0, rb0, lkof, acc);
        __syncthreads();
    }
    epi128<1>(acc, bias, H, H, M, 128, bm, 0, w & 3, w >> 2, lane);
}

// ---------------- segment mean ----------------
__global__ void zero_kernel(float* __restrict__ out) {
    int i = blockIdx.x * blockDim.x + threadIdx.x;
    if (i < NCELL * CLN) out[i] = 0.0f;
    else if (i < NCELL * CLN + NCELL) g_cnt[i - NCELL * CLN] = 0.0f;
}

__global__ void scatter_kernel(float* __restrict__ out) {
    int idx = blockIdx.x * blockDim.x + threadIdx.x;
    if (idx >= NP * 512) return;
    int n = idx >> 9;
    int j = idx & 511;
    int cell = g_flat[n];
    atomicAdd(out + (size_t)cell * 512 + j, g_y[idx]);
    if (j == 0) atomicAdd(&g_cnt[cell], 1.0f);
}

__global__ void div_kernel(float* __restrict__ out) {
    int i = blockIdx.x * blockDim.x + threadIdx.x;
    if (i >= NCELL * 512) return;
    out[i] *= 1.0f / fmaxf(g_cnt[i >> 9], 1.0f);
}

// ---------------- driver ----------------
extern "C" void kernel_launch(void* const* d_in, const int* in_sizes, int n_in,
                              void* d_out, int out_size) {
    const float* x      = (const float*)d_in[0];
    const float* W_emb  = (const float*)d_in[1];
    const float* b_emb  = (const float*)d_in[2];
    const float* ln1_s  = (const float*)d_in[3];
    const float* ln1_b  = (const float*)d_in[4];
    const float* Wqkv   = (const float*)d_in[5];
    const float* bqkv   = (const float*)d_in[6];
    const float* Wo     = (const float*)d_in[7];
    const float* bo     = (const float*)d_in[8];
    const float* ln2_s  = (const float*)d_in[9];
    const float* ln2_b  = (const float*)d_in[10];
    const float* Wf1    = (const float*)d_in[11];
    const float* bf1    = (const float*)d_in[12];
    const float* Wf2    = (const float*)d_in[13];
    const float* bf2    = (const float*)d_in[14];
    const float* W_comb = (const float*)d_in[15];
    const float* b_comb = (const float*)d_in[16];
    float* out = (float*)d_out;

    float *p_feat, *p_h, *p_qkv, *p_gel, *p_y, *p_wt;
    cudaGetSymbolAddress((void**)&p_feat, g_feat);
    cudaGetSymbolAddress((void**)&p_h,    g_h);
    cudaGetSymbolAddress((void**)&p_qkv,  g_qkv);
    cudaGetSymbolAddress((void**)&p_gel,  g_gel);
    cudaGetSymbolAddress((void**)&p_y,    g_y);
    cudaGetSymbolAddress((void**)&p_wt,   g_wt);

    const int SMEM_G  = 73728;    // generic
    const int SMEM_Q  = 110592;   // lnA / attn
    static bool attr_done = false;
    if (!attr_done) {
        cudaFuncSetAttribute((const void*)gemm_tc<0,false>, cudaFuncAttributeMaxDynamicSharedMemorySize, SMEM_G);
        cudaFuncSetAttribute((const void*)gemm_tc<1,false>, cudaFuncAttributeMaxDynamicSharedMemorySize, SMEM_G);
        cudaFuncSetAttribute((const void*)gemm_tc<0,true>,  cudaFuncAttributeMaxDynamicSharedMemorySize, SMEM_G);
        cudaFuncSetAttribute((const void*)gemm_lnA<0>, cudaFuncAttributeMaxDynamicSharedMemorySize, SMEM_Q);
        cudaFuncSetAttribute((const void*)gemm_lnA<2>, cudaFuncAttributeMaxDynamicSharedMemorySize, SMEM_Q);
        cudaFuncSetAttribute((const void*)gemm_attn,   cudaFuncAttributeMaxDynamicSharedMemorySize, SMEM_Q);
        attr_done = true;
    }

    const int TB = 256;

    // weight offsets (floats) in g_wt
    float* wembT  = p_wt + 0;
    float* wqkvT0 = p_wt + 40960;
    float* wqkvT1 = p_wt + 90112;
    float* woT0   = p_wt + 139264;
    float* woT1   = p_wt + 155648;
    float* wf1T0  = p_wt + 172032;
    float* wf1T1  = p_wt + 237568;
    float* wf2T0  = p_wt + 303104;
    float* wf2T1  = p_wt + 368640;
    float* wcombT = p_wt + 434176;

    wconv<<<(696320 + TB - 1) / TB, TB>>>(W_emb, Wqkv, Wo, Wf1, Wf2, W_comb);
    feat_kernel<<<(NP + TB - 1) / TB, TB>>>(x);

    // embedding
    gemm_tc<0,false><<<dim3(4, (NP + 127) / 128), TB, SMEM_G>>>(
        p_feat, wembT, b_emb, nullptr, p_h, NP, 512, 80, 80, 80);

    const float* wqkvT[2] = {wqkvT0, wqkvT1};
    const float* woT[2]   = {woT0, woT1};
    const float* wf1T[2]  = {wf1T0, wf1T1};
    const float* wf2T[2]  = {wf2T0, wf2T1};
    const int MB = (NTOK + 127) / 128;   // 2048

    for (int i = 0; i < 2; i++) {
        // LN1 + QKV (A resident, loops 3 n-blocks)
        gemm_lnA<0><<<dim3(1, MB), TB, SMEM_Q>>>(p_h, wqkvT[i], bqkv + i * 384,
                                                 ln1_s + i * 128, ln1_b + i * 128,
                                                 p_qkv, NTOK, 384);
        // attention + o-proj + residual
        gemm_attn<<<dim3(1, MB), TB, SMEM_Q>>>(p_qkv, woT[i], bo + i * 128, p_h, NTOK);
        // LN2 + FF1 + GELU (A resident, loops 4 n-blocks) -> g_gel
        gemm_lnA<2><<<dim3(1, MB), TB, SMEM_Q>>>(p_h, wf1T[i], bf1 + i * 512,
                                                 ln2_s + i * 128, ln2_b + i * 128,
                                                 p_gel, NTOK, 512);
        // FF2 + residual
        gemm_tc<1,false><<<dim3(1, MB), TB, SMEM_G>>>(p_gel, wf2T[i], bf2 + i * 128,
                                                      p_h, p_h, NTOK, 128, 512, 512, 512);
    }

    // head
    gemm_tc<0,true><<<dim3(4, (NP + 127) / 128), TB, SMEM_G>>>(
        p_h, wcombT, b_comb, nullptr, p_y, NP, 512, 512, 512, 512);

    // segment mean
    zero_kernel<<<(NCELL * CLN + NCELL + TB - 1) / TB, TB>>>(out);
    scatter_kernel<<<(NP * 512 + TB - 1) / TB, TB>>>(out);
    div_kernel<<<(NCELL * 512 + TB - 1) / TB, TB>>>(out);
}

// round 8
// speedup vs baseline: 1.4677x; 1.3746x over previous
#include <cuda_runtime.h>
#include <cuda_fp16.h>
#include <math.h>
#include <stdint.h>

#define NP    65534
#define NTOK  (NP*4)          // 262136 tokens
#define GH    180
#define GW    360
#define NCELL (GH*GW)         // 64800
#define CLN   512

#define SMSB 80               // bytes per smem row (32 fp16 = 64B + 16B pad)
#define CHB  (128*SMSB)       // 10240 bytes per 128x32 fp16 chunk

// ---------------- scratch (device globals: no allocation allowed) ----------------
__device__ __half g_feat[(size_t)NP*96];     // 75 used + zero pad to 96 (fp16)
__device__ int    g_flat[NP];
__device__ float  g_h   [(size_t)NTOK*128];  // transformer state (fp32)
__device__ __half g_h16 [(size_t)NTOK*128];  // final h in fp16 (head GEMM A)
__device__ float  g_qkv [(size_t)NTOK*384];
__device__ __half g_gel [(size_t)NTOK*512];  // gelu output (fp16)
__device__ float  g_y   [(size_t)NP*512];
__device__ float  g_cnt [NCELL];
__device__ __half g_wt  [704512];            // transposed fp16 weights

// ---------------- small PTX helpers ----------------
__device__ __forceinline__ void cpasync16(uint32_t dst, const void* src, bool pred) {
    int sz = pred ? 16 : 0;      // sz=0 => zero-fill 16 bytes
    asm volatile("cp.async.cg.shared.global [%0], [%1], 16, %2;\n"
                 :: "r"(dst), "l"(src), "r"(sz));
}
__device__ __forceinline__ void cp_commit() {
    asm volatile("cp.async.commit_group;\n" ::);
}
__device__ __forceinline__ void ldm4(uint32_t& r0, uint32_t& r1, uint32_t& r2, uint32_t& r3, uint32_t addr) {
    asm volatile("ldmatrix.sync.aligned.m8n8.x4.shared.b16 {%0,%1,%2,%3}, [%4];\n"
                 : "=r"(r0), "=r"(r1), "=r"(r2), "=r"(r3) : "r"(addr));
}
__device__ __forceinline__ void mma_f16(float* c, const uint32_t* a, uint32_t b0, uint32_t b1) {
    asm volatile("mma.sync.aligned.m16n8k16.row.col.f32.f16.f16.f32 "
                 "{%0,%1,%2,%3}, {%4,%5,%6,%7}, {%8,%9}, {%0,%1,%2,%3};\n"
                 : "+f"(c[0]), "+f"(c[1]), "+f"(c[2]), "+f"(c[3])
                 : "r"(a[0]), "r"(a[1]), "r"(a[2]), "r"(a[3]), "r"(b0), "r"(b1));
}
__device__ __forceinline__ float gelu_t(float u) {
    return 0.5f * u * (1.0f + tanhf(0.7978845608028654f * (u + 0.044715f * u * u * u)));
}

// 128x128x32 fp16 mma on one k-chunk. aBase/bBase: smem byte addr of 128x32 chunk.
__device__ __forceinline__ void mma_tile16(uint32_t aBase, uint32_t bBase,
                                           int ra0, int rb0, int lk2,
                                           float acc[2][8][4]) {
    #pragma unroll
    for (int kk = 0; kk < 32; kk += 16) {
        uint32_t a[2][4];
        #pragma unroll
        for (int mi = 0; mi < 2; mi++)
            ldm4(a[mi][0], a[mi][1], a[mi][2], a[mi][3],
                 aBase + (uint32_t)((ra0 + mi * 16) * SMSB + (kk + lk2) * 2));
        uint32_t b0[8], b1[8];
        #pragma unroll
        for (int np = 0; np < 4; np++) {
            uint32_t r0, r1, r2, r3;
            ldm4(r0, r1, r2, r3,
                 bBase + (uint32_t)((rb0 + np * 16) * SMSB + (kk + lk2) * 2));
            b0[2*np] = r0; b0[2*np+1] = r1;
            b1[2*np] = r2; b1[2*np+1] = r3;
        }
        #pragma unroll
        for (int mi = 0; mi < 2; mi++)
            #pragma unroll
            for (int ni = 0; ni < 8; ni++)
                mma_f16(acc[mi][ni], a[mi], b0[ni], b1[ni]);
    }
}

// epilogue for 128-row tiles, warp layout 4x2 (warp tile 32x64)
template<int EPI, bool OUT16>   // EPI: 0=bias, 1=bias+residual, 2=bias+gelu
__device__ __forceinline__ void epi12816(float acc[2][8][4], const float* __restrict__ bias,
                                         const float* __restrict__ R, void* __restrict__ C,
                                         int M, int N, int bm, int bn, int wm, int wn, int lane) {
    const int row0 = bm + wm * 32 + (lane >> 2);
    const int col0 = bn + wn * 64 + (lane & 3) * 2;
    #pragma unroll
    for (int mi = 0; mi < 2; mi++) {
        #pragma unroll
        for (int half = 0; half < 2; half++) {
            int gm = row0 + mi * 16 + half * 8;
            if (gm >= M) continue;
            #pragma unroll
            for (int ni = 0; ni < 8; ni++) {
                int gn = col0 + ni * 8;
                float v0 = acc[mi][ni][half*2 + 0] + bias[gn];
                float v1 = acc[mi][ni][half*2 + 1] + bias[gn + 1];
                if (EPI == 1) {
                    const float2 rr = *(const float2*)(R + (size_t)gm * N + gn);
                    v0 += rr.x; v1 += rr.y;
                }
                if (EPI == 2) { v0 = gelu_t(v0); v1 = gelu_t(v1); }
                if (OUT16) {
                    *(__half2*)((__half*)C + (size_t)gm * N + gn) = __floats2half2_rn(v0, v1);
                } else {
                    float2 o; o.x = v0; o.y = v1;
                    *(float2*)((float*)C + (size_t)gm * N + gn) = o;
                }
            }
        }
    }
}

// ---------------- feature build + grid index (fp16 output) ----------------
__global__ void feat_kernel(const float* __restrict__ x) {
    int i = blockIdx.x * blockDim.x + threadIdx.x;
    if (i >= NP) return;
    const float* xr = x + (size_t)i * 24;
    float lat = xr[0];
    if (lat == -90.0f) lat += 0.0001f;
    float lon = xr[1];
    float t   = xr[2];

    int lati = (int)floorf(90.0f - lat);
    int loni = (int)fmodf(180.0f + floorf(lon + 180.0f), 360.0f);
    g_flat[i] = lati * GW + loni;

    __half* f = g_feat + (size_t)i * 96;
    f[0] = __float2half_rn(lat * (1.0f/90.0f));
    f[1] = __float2half_rn(lon * (1.0f/180.0f));
    f[2] = __float2half_rn(t   * (1.0f/12.0f));
    #pragma unroll
    for (int j = 3; j < 24; j++) f[j] = __float2half_rn(xr[j]);

    float p0 = -lat - floorf(-lat);
    float p1 =  lon - floorf(lon);
    float p2 =  t + 1.0f;
    f[24] = __float2half_rn(p0); f[25] = __float2half_rn(p1); f[26] = __float2half_rn(p2);
    float p[3] = {p0, p1, p2};
    #pragma unroll
    for (int c = 0; c < 3; c++) {
        float fr = 3.14159274101257324f;
        #pragma unroll
        for (int k = 0; k < 8; k++) {
            float ang = p[c] * fr;
            f[27 + c*8 + k] = __float2half_rn(sinf(ang));
            f[51 + c*8 + k] = __float2half_rn(cosf(ang));
            fr *= 2.0f;
        }
    }
    #pragma unroll
    for (int j = 75; j < 96; j++) f[j] = __float2half_rn(0.0f);
}

// ---------------- all-in-one weight transpose + fp16 round ----------------
__global__ void wconv(const float* __restrict__ W_emb, const float* __restrict__ Wqkv,
                      const float* __restrict__ Wo, const float* __restrict__ Wf1,
                      const float* __restrict__ Wf2, const float* __restrict__ W_comb) {
    int idx = blockIdx.x * blockDim.x + threadIdx.x;
    if (idx >= 704512) return;
    const float* srcs[6] = {W_emb, Wqkv, Wo, Wf1, Wf2, W_comb};
    const int sel [10] = {0,1,1,2,2,3,3,4,4,5};
    const int soff[10] = {0,0,49152,0,16384,0,65536,0,65536,0};
    const int Kt  [10] = {75,128,128,128,128,128,128,512,512,512};
    const int Nt  [10] = {512,384,384,128,128,512,512,128,128,512};
    const int Kp  [10] = {96,128,128,128,128,128,128,512,512,512};
    const int dst [10] = {0,49152,98304,147456,163840,180224,245760,311296,376832,442368};
    int m = 0;
    #pragma unroll
    for (int i = 1; i < 10; i++) if (idx >= dst[i]) m = i;
    int local = idx - dst[m];
    int n = local / Kp[m];
    int k = local - n * Kp[m];
    float v = (k < Kt[m]) ? srcs[sel[m]][soff[m] + (size_t)k * Nt[m] + n] : 0.0f;
    g_wt[idx] = __float2half_rn(v);
}

// ---------------- generic fp16 GEMM (emb K=96, ff2 K=512, head K=512) ----------------
template<int EPI, bool OUT16>
__global__ void __launch_bounds__(256, 2)
gemm_tc16(const __half* __restrict__ A, const __half* __restrict__ Bt,
          const float* __restrict__ bias, const float* __restrict__ R,
          void* __restrict__ C, int M, int N, int K, int lda, int ldb) {
    extern __shared__ char smc[];
    const int tid  = threadIdx.x;
    const int lane = tid & 31;
    const int w    = tid >> 5;
    const int wm   = w & 3;
    const int wn   = w >> 2;
    const int bm   = blockIdx.y * 128;
    const int bn   = blockIdx.x * 128;

    const uint32_t sA = (uint32_t)__cvta_generic_to_shared(smc);
    const uint32_t sB = sA + 2*CHB;

    float acc[2][8][4];
    #pragma unroll
    for (int mi = 0; mi < 2; mi++)
        #pragma unroll
        for (int ni = 0; ni < 8; ni++)
            #pragma unroll
            for (int r = 0; r < 4; r++) acc[mi][ni][r] = 0.0f;

    const int lrow = (lane & 7) + ((lane >> 3) & 1) * 8;
    const int lk2  = ((lane >> 4) & 1) * 8;
    const int ra0  = wm * 32 + lrow;
    const int rb0  = wn * 64 + lrow;
    const int niter = K >> 5;

    auto load_stage = [&](int s, int k0) {
        #pragma unroll
        for (int l = 0; l < 2; l++) {
            int idx = tid + l * 256;      // 0..511
            int row = idx >> 2;
            int g   = idx & 3;
            bool pa = (bm + row) < M;
            const void* src = pa ? (const void*)(A + (size_t)(bm + row) * lda + k0 + g * 8)
                                 : (const void*)A;
            cpasync16(sA + (uint32_t)(s*CHB + row*SMSB + g*16), src, pa);
        }
        #pragma unroll
        for (int l = 0; l < 2; l++) {
            int idx = tid + l * 256;
            int row = idx >> 2;
            int g   = idx & 3;
            cpasync16(sB + (uint32_t)(s*CHB + row*SMSB + g*16),
                      Bt + (size_t)(bn + row) * ldb + k0 + g * 8, true);
        }
        cp_commit();
    };

    load_stage(0, 0);
    for (int it = 0; it < niter; it++) {
        if (it + 1 < niter) {
            load_stage((it + 1) & 1, (it + 1) * 32);
            asm volatile("cp.async.wait_group 1;\n" ::);
        } else {
            asm volatile("cp.async.wait_group 0;\n" ::);
        }
        __syncthreads();
        const int s = it & 1;
        mma_tile16(sA + (uint32_t)(s*CHB), sB + (uint32_t)(s*CHB), ra0, rb0, lk2, acc);
        __syncthreads();
    }
    epi12816<EPI, OUT16>(acc, bias, R, C, M, N, bm, bn, wm, wn, lane);
}

// ---------------- fused LN + GEMM over all n-blocks (A resident fp16): K=128 ----------------
// grid (1, M/128). EPI=0/OUT16=false -> qkv (N=384 fp32). EPI=2/OUT16=true -> gel (N=512 fp16).
template<int EPI, bool OUT16>
__global__ void __launch_bounds__(256, 2)
lnA16(const float* __restrict__ H, const __half* __restrict__ Bt,
      const float* __restrict__ bias, const float* __restrict__ lns,
      const float* __restrict__ lnb, void* __restrict__ C, int M, int N) {
    extern __shared__ char smc[];
    const int tid  = threadIdx.x;
    const int lane = tid & 31;
    const int w    = tid >> 5;
    const int bm   = blockIdx.y * 128;

    const uint32_t sA = (uint32_t)__cvta_generic_to_shared(smc);
    const uint32_t sB = sA + 4*CHB;

    auto loadB = [&](int s) {
        int nb = s >> 2, kc = s & 3, buf = s & 1;
        #pragma unroll
        for (int l = 0; l < 2; l++) {
            int idx = tid + l * 256;
            int row = idx >> 2;
            int g   = idx & 3;
            cpasync16(sB + (uint32_t)(buf*CHB + row*SMSB + g*16),
                      Bt + (size_t)(nb * 128 + row) * 128 + kc * 32 + g * 8, true);
        }
        cp_commit();
    };

    loadB(0);

    // LayerNorm: warp w rows w*16..+15; lane covers k = lane*4..+3; write fp16 to A tile
    {
        const float4 sc4 = ((const float4*)lns)[lane];
        const float4 bc4 = ((const float4*)lnb)[lane];
        #pragma unroll
        for (int rr = 0; rr < 16; rr++) {
            int row = w * 16 + rr;
            int gm  = bm + row;
            float4 v = make_float4(0,0,0,0);
            if (gm < M) v = *(const float4*)(H + (size_t)gm * 128 + lane * 4);
            float sum = v.x + v.y + v.z + v.w;
            float sq  = v.x*v.x + v.y*v.y + v.z*v.z + v.w*v.w;
            #pragma unroll
            for (int o = 16; o > 0; o >>= 1) {
                sum += __shfl_xor_sync(0xffffffffu, sum, o);
                sq  += __shfl_xor_sync(0xffffffffu, sq,  o);
            }
            float mean = sum * (1.0f/128.0f);
            float var  = sq  * (1.0f/128.0f) - mean * mean;
            float r = rsqrtf(var + 1e-5f);
            float o0 = (v.x - mean) * r * sc4.x + bc4.x;
            float o1 = (v.y - mean) * r * sc4.y + bc4.y;
            float o2 = (v.z - mean) * r * sc4.z + bc4.z;
            float o3 = (v.w - mean) * r * sc4.w + bc4.w;
            __half2* d = (__half2*)(smc + (lane >> 3) * CHB + row * SMSB + (lane & 7) * 8);
            d[0] = __floats2half2_rn(o0, o1);
            d[1] = __floats2half2_rn(o2, o3);
        }
    }
    __syncthreads();

    const int lrow = (lane & 7) + ((lane >> 3) & 1) * 8;
    const int lk2  = ((lane >> 4) & 1) * 8;
    const int ra0  = (w & 3) * 32 + lrow;
    const int rb0  = (w >> 2) * 64 + lrow;

    float acc[2][8][4];
    const int nst = (N >> 7) * 4;
    for (int s = 0; s < nst; s++) {
        if (s + 1 < nst) {
            loadB(s + 1);
            asm volatile("cp.async.wait_group 1;\n" ::);
        } else {
            asm volatile("cp.async.wait_group 0;\n" ::);
        }
        __syncthreads();
        if ((s & 3) == 0) {
            #pragma unroll
            for (int mi = 0; mi < 2; mi++)
                #pragma unroll
                for (int ni = 0; ni < 8; ni++)
                    #pragma unroll
                    for (int r = 0; r < 4; r++) acc[mi][ni][r] = 0.0f;
        }
        mma_tile16(sA + (uint32_t)((s & 3)*CHB), sB + (uint32_t)((s & 1)*CHB),
                   ra0, rb0, lk2, acc);
        if ((s & 3) == 3)
            epi12816<EPI, OUT16>(acc, bias, nullptr, C, M, N, bm, (s >> 2) * 128,
                                 w & 3, w >> 2, lane);
        __syncthreads();
    }
}

// ---------------- fused attention + o-proj (+residual): N=128, K=128 ----------------
__global__ void __launch_bounds__(256, 2)
attn16(const float* __restrict__ qkv, const __half* __restrict__ Bt,
       const float* __restrict__ bias, float* __restrict__ H, int M) {
    extern __shared__ char smc[];
    const int tid  = threadIdx.x;
    const int lane = tid & 31;
    const int w    = tid >> 5;
    const int bm   = blockIdx.y * 128;

    const uint32_t sA = (uint32_t)__cvta_generic_to_shared(smc);
    const uint32_t sB = sA + 4*CHB;

    auto loadB = [&](int kc, int buf) {
        #pragma unroll
        for (int l = 0; l < 2; l++) {
            int idx = tid + l * 256;
            int row = idx >> 2;
            int g   = idx & 3;
            cpasync16(sB + (uint32_t)(buf*CHB + row*SMSB + g*16),
                      Bt + (size_t)row * 128 + kc * 32 + g * 8, true);
        }
        cp_commit();
    };

    loadB(0, 0);

    // attention: thread owns (point, head); writes 16 fp16 per token row into A tile
    {
        int p_local = tid >> 3;
        int hh = tid & 7;
        int p = (bm >> 2) + p_local;
        if (p < NP) {
            const float* base = qkv + (size_t)p * 1536 + hh * 16;
            #pragma unroll
            for (int qi = 0; qi < 4; qi++) {
                float q[16];
                const float4* qp = (const float4*)(base + qi * 384);
                #pragma unroll
                for (int c = 0; c < 4; c++) {
                    float4 t = qp[c];
                    q[c*4+0] = t.x; q[c*4+1] = t.y; q[c*4+2] = t.z; q[c*4+3] = t.w;
                }
                float sc[4];
                float mx = -1e30f;
                #pragma unroll
                for (int ki = 0; ki < 4; ki++) {
                    const float4* kp = (const float4*)(base + 128 + ki * 384);
                    float s = 0.0f;
                    #pragma unroll
                    for (int c = 0; c < 4; c++) {
                        float4 t = kp[c];
                        s += q[c*4+0]*t.x + q[c*4+1]*t.y + q[c*4+2]*t.z + q[c*4+3]*t.w;
                    }
                    s *= 0.25f;
                    sc[ki] = s;
                    mx = fmaxf(mx, s);
                }
                float sum = 0.0f;
                #pragma unroll
                for (int ki = 0; ki < 4; ki++) { sc[ki] = expf(sc[ki] - mx); sum += sc[ki]; }
                float inv = 1.0f / sum;
                float acco[16];
                #pragma unroll
                for (int d = 0; d < 16; d++) acco[d] = 0.0f;
                #pragma unroll
                for (int ki = 0; ki < 4; ki++) {
                    float wv = sc[ki] * inv;
                    const float4* vp = (const float4*)(base + 256 + ki * 384);
                    #pragma unroll
                    for (int c = 0; c < 4; c++) {
                        float4 t = vp[c];
                        acco[c*4+0] += wv * t.x; acco[c*4+1] += wv * t.y;
                        acco[c*4+2] += wv * t.z; acco[c*4+3] += wv * t.w;
                    }
                }
                int row = p_local * 4 + qi;
                __half2* d = (__half2*)(smc + (hh >> 1) * CHB + row * SMSB + (hh & 1) * 32);
                #pragma unroll
                for (int c = 0; c < 8; c++)
                    d[c] = __floats2half2_rn(acco[2*c], acco[2*c+1]);
            }
        } else {
            int p_l = tid >> 3, hh2 = tid & 7;
            #pragma unroll
            for (int qi = 0; qi < 4; qi++) {
                int row = p_l * 4 + qi;
                __half2* d = (__half2*)(smc + (hh2 >> 1) * CHB + row * SMSB + (hh2 & 1) * 32);
                #pragma unroll
                for (int c = 0; c < 8; c++) d[c] = __floats2half2_rn(0.0f, 0.0f);
            }
        }
    }

    float acc[2][8][4];
    #pragma unroll
    for (int mi = 0; mi < 2; mi++)
        #pragma unroll
        for (int ni = 0; ni < 8; ni++)
            #pragma unroll
            for (int r = 0; r < 4; r++) acc[mi][ni][r] = 0.0f;

    const int lrow = (lane & 7) + ((lane >> 3) & 1) * 8;
    const int lk2  = ((lane >> 4) & 1) * 8;
    const int ra0  = (w & 3) * 32 + lrow;
    const int rb0  = (w >> 2) * 64 + lrow;

    for (int kc = 0; kc < 4; kc++) {
        if (kc < 3) {
            loadB(kc + 1, (kc + 1) & 1);
            asm volatile("cp.async.wait_group 1;\n" ::);
        } else {
            asm volatile("cp.async.wait_group 0;\n" ::);
        }
        __syncthreads();
        mma_tile16(sA + (uint32_t)(kc*CHB), sB + (uint32_t)((kc & 1)*CHB),
                   ra0, rb0, lk2, acc);
        __syncthreads();
    }
    epi12816<1, false>(acc, bias, H, H, M, 128, bm, 0, w & 3, w >> 2, lane);
}

// ---------------- segment mean ----------------
__global__ void zero_kernel(float* __restrict__ out) {
    int i = blockIdx.x * blockDim.x + threadIdx.x;
    if (i < NCELL * CLN) out[i] = 0.0f;
    else if (i < NCELL * CLN + NCELL) g_cnt[i - NCELL * CLN] = 0.0f;
}

__global__ void scatter_kernel(float* __restrict__ out) {
    int idx = blockIdx.x * blockDim.x + threadIdx.x;
    if (idx >= NP * 512) return;
    int n = idx >> 9;
    int j = idx & 511;
    int cell = g_flat[n];
    atomicAdd(out + (size_t)cell * 512 + j, g_y[idx]);
    if (j == 0) atomicAdd(&g_cnt[cell], 1.0f);
}

__global__ void div_kernel(float* __restrict__ out) {
    int i = blockIdx.x * blockDim.x + threadIdx.x;
    if (i >= NCELL * 512) return;
    out[i] *= 1.0f / fmaxf(g_cnt[i >> 9], 1.0f);
}

// ---------------- driver ----------------
extern "C" void kernel_launch(void* const* d_in, const int* in_sizes, int n_in,
                              void* d_out, int out_size) {
    const float* x      = (const float*)d_in[0];
    const float* W_emb  = (const float*)d_in[1];
    const float* b_emb  = (const float*)d_in[2];
    const float* ln1_s  = (const float*)d_in[3];
    const float* ln1_b  = (const float*)d_in[4];
    const float* Wqkv   = (const float*)d_in[5];
    const float* bqkv   = (const float*)d_in[6];
    const float* Wo     = (const float*)d_in[7];
    const float* bo     = (const float*)d_in[8];
    const float* ln2_s  = (const float*)d_in[9];
    const float* ln2_b  = (const float*)d_in[10];
    const float* Wf1    = (const float*)d_in[11];
    const float* bf1    = (const float*)d_in[12];
    const float* Wf2    = (const float*)d_in[13];
    const float* bf2    = (const float*)d_in[14];
    const float* W_comb = (const float*)d_in[15];
    const float* b_comb = (const float*)d_in[16];
    float* out = (float*)d_out;

    float *p_h, *p_qkv, *p_y;
    __half *p_feat, *p_h16, *p_gel, *p_wt;
    cudaGetSymbolAddress((void**)&p_feat, g_feat);
    cudaGetSymbolAddress((void**)&p_h,    g_h);
    cudaGetSymbolAddress((void**)&p_h16,  g_h16);
    cudaGetSymbolAddress((void**)&p_qkv,  g_qkv);
    cudaGetSymbolAddress((void**)&p_gel,  g_gel);
    cudaGetSymbolAddress((void**)&p_y,    g_y);
    cudaGetSymbolAddress((void**)&p_wt,   g_wt);

    const int SMEM_G = 4 * CHB;   // 40960
    const int SMEM_F = 6 * CHB;   // 61440
    static bool attr_done = false;
    if (!attr_done) {
        cudaFuncSetAttribute((const void*)gemm_tc16<0,false>, cudaFuncAttributeMaxDynamicSharedMemorySize, SMEM_G);
        cudaFuncSetAttribute((const void*)gemm_tc16<1,false>, cudaFuncAttributeMaxDynamicSharedMemorySize, SMEM_G);
        cudaFuncSetAttribute((const void*)gemm_tc16<1,true>,  cudaFuncAttributeMaxDynamicSharedMemorySize, SMEM_G);
        cudaFuncSetAttribute((const void*)lnA16<0,false>, cudaFuncAttributeMaxDynamicSharedMemorySize, SMEM_F);
        cudaFuncSetAttribute((const void*)lnA16<2,true>,  cudaFuncAttributeMaxDynamicSharedMemorySize, SMEM_F);
        cudaFuncSetAttribute((const void*)attn16,         cudaFuncAttributeMaxDynamicSharedMemorySize, SMEM_F);
        attr_done = true;
    }

    const int TB = 256;

    // fp16 weight offsets in g_wt
    __half* wembT  = p_wt + 0;        // [512][96]
    __half* wqkvT0 = p_wt + 49152;    // [384][128]
    __half* wqkvT1 = p_wt + 98304;
    __half* woT0   = p_wt + 147456;   // [128][128]
    __half* woT1   = p_wt + 163840;
    __half* wf1T0  = p_wt + 180224;   // [512][128]
    __half* wf1T1  = p_wt + 245760;
    __half* wf2T0  = p_wt + 311296;   // [128][512]
    __half* wf2T1  = p_wt + 376832;
    __half* wcombT = p_wt + 442368;   // [512][512]

    wconv<<<(704512 + TB - 1) / TB, TB>>>(W_emb, Wqkv, Wo, Wf1, Wf2, W_comb);
    feat_kernel<<<(NP + TB - 1) / TB, TB>>>(x);

    // embedding: feat(NP x 96 fp16) @ W_emb -> h (fp32)
    gemm_tc16<0,false><<<dim3(4, (NP + 127) / 128), TB, SMEM_G>>>(
        p_feat, wembT, b_emb, nullptr, p_h, NP, 512, 96, 96, 96);

    const __half* wqkvT[2] = {wqkvT0, wqkvT1};
    const __half* woT[2]   = {woT0, woT1};
    const __half* wf1T[2]  = {wf1T0, wf1T1};
    const __half* wf2T[2]  = {wf2T0, wf2T1};
    const int MB = (NTOK + 127) / 128;   // 2048

    for (int i = 0; i < 2; i++) {
        // LN1 + QKV
        lnA16<0,false><<<dim3(1, MB), TB, SMEM_F>>>(p_h, wqkvT[i], bqkv + i * 384,
                                                    ln1_s + i * 128, ln1_b + i * 128,
                                                    p_qkv, NTOK, 384);
        // attention + o-proj + residual
        attn16<<<dim3(1, MB), TB, SMEM_F>>>(p_qkv, woT[i], bo + i * 128, p_h, NTOK);
        // LN2 + FF1 + GELU -> g_gel (fp16)
        lnA16<2,true><<<dim3(1, MB), TB, SMEM_F>>>(p_h, wf1T[i], bf1 + i * 512,
                                                   ln2_s + i * 128, ln2_b + i * 128,
                                                   p_gel, NTOK, 512);
        // FF2 + residual; last layer also emits fp16 h for the head
        if (i == 0)
            gemm_tc16<1,false><<<dim3(1, MB), TB, SMEM_G>>>(p_gel, wf2T[i], bf2 + i * 128,
                                                            p_h, p_h, NTOK, 128, 512, 512, 512);
        else
            gemm_tc16<1,true><<<dim3(1, MB), TB, SMEM_G>>>(p_gel, wf2T[i], bf2 + i * 128,
                                                           p_h, p_h16, NTOK, 128, 512, 512, 512);
    }

    // head: h16(NP x 512) @ W_comb -> y (fp32)
    gemm_tc16<0,false><<<dim3(4, (NP + 127) / 128), TB, SMEM_G>>>(
        p_h16, wcombT, b_comb, nullptr, p_y, NP, 512, 512, 512, 512);

    // segment mean
    zero_kernel<<<(NCELL * CLN + NCELL + TB - 1) / TB, TB>>>(out);
    scatter_kernel<<<(NP * 512 + TB - 1) / TB, TB>>>(out);
    div_kernel<<<(NCELL * 512 + TB - 1) / TB, TB>>>(out);
}

// round 9
// speedup vs baseline: 1.5957x; 1.0872x over previous
#include <cuda_runtime.h>
#include <cuda_fp16.h>
#include <math.h>
#include <stdint.h>

#define NP    65534
#define NTOK  (NP*4)          // 262136 tokens
#define GH    180
#define GW    360
#define NCELL (GH*GW)         // 64800
#define CLN   512

#define SMSB 80               // bytes per smem row (32 fp16 = 64B + 16B pad)
#define CHB  (128*SMSB)       // 10240 bytes per 128x32 fp16 chunk

// ---------------- scratch (device globals: no allocation allowed) ----------------
__device__ __half g_feat[(size_t)NP*96];     // 75 used + zero pad to 96 (fp16)
__device__ int    g_flat[NP];
__device__ float  g_h   [(size_t)NTOK*128];  // transformer state (fp32)
__device__ __half g_h16 [(size_t)NTOK*128];  // final h in fp16 (head GEMM A)
__device__ __half g_qkv [(size_t)NTOK*384];  // fp16 qkv
__device__ __half g_gel [(size_t)NTOK*512];  // gelu output (fp16)
__device__ float  g_cnt [NCELL];
__device__ __half g_wt  [704512];            // transposed fp16 weights

// ---------------- small PTX helpers ----------------
__device__ __forceinline__ void cpasync16(uint32_t dst, const void* src, bool pred) {
    int sz = pred ? 16 : 0;      // sz=0 => zero-fill 16 bytes
    asm volatile("cp.async.cg.shared.global [%0], [%1], 16, %2;\n"
                 :: "r"(dst), "l"(src), "r"(sz));
}
__device__ __forceinline__ void cp_commit() {
    asm volatile("cp.async.commit_group;\n" ::);
}
__device__ __forceinline__ void ldm4(uint32_t& r0, uint32_t& r1, uint32_t& r2, uint32_t& r3, uint32_t addr) {
    asm volatile("ldmatrix.sync.aligned.m8n8.x4.shared.b16 {%0,%1,%2,%3}, [%4];\n"
                 : "=r"(r0), "=r"(r1), "=r"(r2), "=r"(r3) : "r"(addr));
}
__device__ __forceinline__ void mma_f16(float* c, const uint32_t* a, uint32_t b0, uint32_t b1) {
    asm volatile("mma.sync.aligned.m16n8k16.row.col.f32.f16.f16.f32 "
                 "{%0,%1,%2,%3}, {%4,%5,%6,%7}, {%8,%9}, {%0,%1,%2,%3};\n"
                 : "+f"(c[0]), "+f"(c[1]), "+f"(c[2]), "+f"(c[3])
                 : "r"(a[0]), "r"(a[1]), "r"(a[2]), "r"(a[3]), "r"(b0), "r"(b1));
}
__device__ __forceinline__ float gelu_t(float u) {
    return 0.5f * u * (1.0f + tanhf(0.7978845608028654f * (u + 0.044715f * u * u * u)));
}
// load 16 fp16 -> float[16] (two 16B vector loads)
__device__ __forceinline__ void ld16h(const __half* p, float* o) {
    uint4 u0 = *(const uint4*)p;
    uint4 u1 = *(const uint4*)(p + 8);
    const uint32_t* w0 = (const uint32_t*)&u0;
    const uint32_t* w1 = (const uint32_t*)&u1;
    #pragma unroll
    for (int i = 0; i < 4; i++) {
        float2 f = __half22float2(*(const __half2*)&w0[i]);
        o[2*i+0] = f.x; o[2*i+1] = f.y;
    }
    #pragma unroll
    for (int i = 0; i < 4; i++) {
        float2 f = __half22float2(*(const __half2*)&w1[i]);
        o[8+2*i+0] = f.x; o[8+2*i+1] = f.y;
    }
}

// 128x128x32 fp16 mma on one k-chunk. aBase/bBase: smem byte addr of 128x32 chunk.
__device__ __forceinline__ void mma_tile16(uint32_t aBase, uint32_t bBase,
                                           int ra0, int rb0, int lk2,
                                           float acc[2][8][4]) {
    #pragma unroll
    for (int kk = 0; kk < 32; kk += 16) {
        uint32_t a[2][4];
        #pragma unroll
        for (int mi = 0; mi < 2; mi++)
            ldm4(a[mi][0], a[mi][1], a[mi][2], a[mi][3],
                 aBase + (uint32_t)((ra0 + mi * 16) * SMSB + (kk + lk2) * 2));
        uint32_t b0[8], b1[8];
        #pragma unroll
        for (int np = 0; np < 4; np++) {
            uint32_t r0, r1, r2, r3;
            ldm4(r0, r1, r2, r3,
                 bBase + (uint32_t)((rb0 + np * 16) * SMSB + (kk + lk2) * 2));
            b0[2*np] = r0; b0[2*np+1] = r1;
            b1[2*np] = r2; b1[2*np+1] = r3;
        }
        #pragma unroll
        for (int mi = 0; mi < 2; mi++)
            #pragma unroll
            for (int ni = 0; ni < 8; ni++)
                mma_f16(acc[mi][ni], a[mi], b0[ni], b1[ni]);
    }
}

// epilogue for 128-row tiles, warp layout 4x2 (warp tile 32x64)
// EPI: 0=bias, 1=bias+residual, 2=bias+gelu, 3=bias+grid-scatter(atomicAdd)
template<int EPI, bool OUT16>
__device__ __forceinline__ void epi12816(float acc[2][8][4], const float* __restrict__ bias,
                                         const float* __restrict__ R, void* __restrict__ C,
                                         int M, int N, int bm, int bn, int wm, int wn, int lane) {
    const int row0 = bm + wm * 32 + (lane >> 2);
    const int col0 = bn + wn * 64 + (lane & 3) * 2;
    #pragma unroll
    for (int mi = 0; mi < 2; mi++) {
        #pragma unroll
        for (int half = 0; half < 2; half++) {
            int gm = row0 + mi * 16 + half * 8;
            if (gm >= M) continue;
            int cell = (EPI == 3) ? g_flat[gm] : 0;
            #pragma unroll
            for (int ni = 0; ni < 8; ni++) {
                int gn = col0 + ni * 8;
                float v0 = acc[mi][ni][half*2 + 0] + bias[gn];
                float v1 = acc[mi][ni][half*2 + 1] + bias[gn + 1];
                if (EPI == 1) {
                    const float2 rr = *(const float2*)(R + (size_t)gm * N + gn);
                    v0 += rr.x; v1 += rr.y;
                }
                if (EPI == 2) { v0 = gelu_t(v0); v1 = gelu_t(v1); }
                if (EPI == 3) {
                    float* dst = (float*)C + (size_t)cell * CLN + gn;
                    atomicAdd(dst,     v0);
                    atomicAdd(dst + 1, v1);
                } else if (OUT16) {
                    *(__half2*)((__half*)C + (size_t)gm * N + gn) = __floats2half2_rn(v0, v1);
                } else {
                    float2 o; o.x = v0; o.y = v1;
                    *(float2*)((float*)C + (size_t)gm * N + gn) = o;
                }
            }
        }
    }
}

// ---------------- feature build + grid index + counts (fp16 output) ----------------
__global__ void feat_kernel(const float* __restrict__ x) {
    int i = blockIdx.x * blockDim.x + threadIdx.x;
    if (i >= NP) return;
    const float* xr = x + (size_t)i * 24;
    float lat = xr[0];
    if (lat == -90.0f) lat += 0.0001f;
    float lon = xr[1];
    float t   = xr[2];

    int lati = (int)floorf(90.0f - lat);
    int loni = (int)fmodf(180.0f + floorf(lon + 180.0f), 360.0f);
    int cell = lati * GW + loni;
    g_flat[i] = cell;
    atomicAdd(&g_cnt[cell], 1.0f);

    __half* f = g_feat + (size_t)i * 96;
    f[0] = __float2half_rn(lat * (1.0f/90.0f));
    f[1] = __float2half_rn(lon * (1.0f/180.0f));
    f[2] = __float2half_rn(t   * (1.0f/12.0f));
    #pragma unroll
    for (int j = 3; j < 24; j++) f[j] = __float2half_rn(xr[j]);

    float p0 = -lat - floorf(-lat);
    float p1 =  lon - floorf(lon);
    float p2 =  t + 1.0f;
    f[24] = __float2half_rn(p0); f[25] = __float2half_rn(p1); f[26] = __float2half_rn(p2);
    float p[3] = {p0, p1, p2};
    #pragma unroll
    for (int c = 0; c < 3; c++) {
        float fr = 3.14159274101257324f;
        #pragma unroll
        for (int k = 0; k < 8; k++) {
            float ang = p[c] * fr;
            f[27 + c*8 + k] = __float2half_rn(sinf(ang));
            f[51 + c*8 + k] = __float2half_rn(cosf(ang));
            fr *= 2.0f;
        }
    }
    #pragma unroll
    for (int j = 75; j < 96; j++) f[j] = __float2half_rn(0.0f);
}

// ---------------- all-in-one weight transpose + fp16 round ----------------
__global__ void wconv(const float* __restrict__ W_emb, const float* __restrict__ Wqkv,
                      const float* __restrict__ Wo, const float* __restrict__ Wf1,
                      const float* __restrict__ Wf2, const float* __restrict__ W_comb) {
    int idx = blockIdx.x * blockDim.x + threadIdx.x;
    if (idx >= 704512) return;
    const float* srcs[6] = {W_emb, Wqkv, Wo, Wf1, Wf2, W_comb};
    const int sel [10] = {0,1,1,2,2,3,3,4,4,5};
    const int soff[10] = {0,0,49152,0,16384,0,65536,0,65536,0};
    const int Kt  [10] = {75,128,128,128,128,128,128,512,512,512};
    const int Nt  [10] = {512,384,384,128,128,512,512,128,128,512};
    const int Kp  [10] = {96,128,128,128,128,128,128,512,512,512};
    const int dst [10] = {0,49152,98304,147456,163840,180224,245760,311296,376832,442368};
    int m = 0;
    #pragma unroll
    for (int i = 1; i < 10; i++) if (idx >= dst[i]) m = i;
    int local = idx - dst[m];
    int n = local / Kp[m];
    int k = local - n * Kp[m];
    float v = (k < Kt[m]) ? srcs[sel[m]][soff[m] + (size_t)k * Nt[m] + n] : 0.0f;
    g_wt[idx] = __float2half_rn(v);
}

// ---------------- generic fp16 GEMM (emb K=96, ff2 K=512, head K=512) ----------------
template<int EPI, bool OUT16>
__global__ void __launch_bounds__(256, 2)
gemm_tc16(const __half* __restrict__ A, const __half* __restrict__ Bt,
          const float* __restrict__ bias, const float* __restrict__ R,
          void* __restrict__ C, int M, int N, int K, int lda, int ldb) {
    extern __shared__ char smc[];
    const int tid  = threadIdx.x;
    const int lane = tid & 31;
    const int w    = tid >> 5;
    const int wm   = w & 3;
    const int wn   = w >> 2;
    const int bm   = blockIdx.y * 128;
    const int bn   = blockIdx.x * 128;

    const uint32_t sA = (uint32_t)__cvta_generic_to_shared(smc);
    const uint32_t sB = sA + 2*CHB;

    float acc[2][8][4];
    #pragma unroll
    for (int mi = 0; mi < 2; mi++)
        #pragma unroll
        for (int ni = 0; ni < 8; ni++)
            #pragma unroll
            for (int r = 0; r < 4; r++) acc[mi][ni][r] = 0.0f;

    const int lrow = (lane & 7) + ((lane >> 3) & 1) * 8;
    const int lk2  = ((lane >> 4) & 1) * 8;
    const int ra0  = wm * 32 + lrow;
    const int rb0  = wn * 64 + lrow;
    const int niter = K >> 5;

    auto load_stage = [&](int s, int k0) {
        #pragma unroll
        for (int l = 0; l < 2; l++) {
            int idx = tid + l * 256;      // 0..511
            int row = idx >> 2;
            int g   = idx & 3;
            bool pa = (bm + row) < M;
            const void* src = pa ? (const void*)(A + (size_t)(bm + row) * lda + k0 + g * 8)
                                 : (const void*)A;
            cpasync16(sA + (uint32_t)(s*CHB + row*SMSB + g*16), src, pa);
        }
        #pragma unroll
        for (int l = 0; l < 2; l++) {
            int idx = tid + l * 256;
            int row = idx >> 2;
            int g   = idx & 3;
            cpasync16(sB + (uint32_t)(s*CHB + row*SMSB + g*16),
                      Bt + (size_t)(bn + row) * ldb + k0 + g * 8, true);
        }
        cp_commit();
    };

    load_stage(0, 0);
    for (int it = 0; it < niter; it++) {
        if (it + 1 < niter) {
            load_stage((it + 1) & 1, (it + 1) * 32);
            asm volatile("cp.async.wait_group 1;\n" ::);
        } else {
            asm volatile("cp.async.wait_group 0;\n" ::);
        }
        __syncthreads();
        const int s = it & 1;
        mma_tile16(sA + (uint32_t)(s*CHB), sB + (uint32_t)(s*CHB), ra0, rb0, lk2, acc);
        __syncthreads();
    }
    epi12816<EPI, OUT16>(acc, bias, R, C, M, N, bm, bn, wm, wn, lane);
}

// ---------------- fused LN + GEMM over all n-blocks (A resident fp16): K=128 ----------------
// grid (1, M/128). EPI=0/OUT16=true -> qkv fp16 (N=384). EPI=2/OUT16=true -> gel fp16 (N=512).
template<int EPI, bool OUT16>
__global__ void __launch_bounds__(256, 2)
lnA16(const float* __restrict__ H, const __half* __restrict__ Bt,
      const float* __restrict__ bias, const float* __restrict__ lns,
      const float* __restrict__ lnb, void* __restrict__ C, int M, int N) {
    extern __shared__ char smc[];
    const int tid  = threadIdx.x;
    const int lane = tid & 31;
    const int w    = tid >> 5;
    const int bm   = blockIdx.y * 128;

    const uint32_t sA = (uint32_t)__cvta_generic_to_shared(smc);
    const uint32_t sB = sA + 4*CHB;

    auto loadB = [&](int s) {
        int nb = s >> 2, kc = s & 3, buf = s & 1;
        #pragma unroll
        for (int l = 0; l < 2; l++) {
            int idx = tid + l * 256;
            int row = idx >> 2;
            int g   = idx & 3;
            cpasync16(sB + (uint32_t)(buf*CHB + row*SMSB + g*16),
                      Bt + (size_t)(nb * 128 + row) * 128 + kc * 32 + g * 8, true);
        }
        cp_commit();
    };

    loadB(0);

    // LayerNorm: warp w rows w*16..+15; lane covers k = lane*4..+3; write fp16 to A tile
    {
        const float4 sc4 = ((const float4*)lns)[lane];
        const float4 bc4 = ((const float4*)lnb)[lane];
        #pragma unroll
        for (int rr = 0; rr < 16; rr++) {
            int row = w * 16 + rr;
            int gm  = bm + row;
            float4 v = make_float4(0,0,0,0);
            if (gm < M) v = *(const float4*)(H + (size_t)gm * 128 + lane * 4);
            float sum = v.x + v.y + v.z + v.w;
            float sq  = v.x*v.x + v.y*v.y + v.z*v.z + v.w*v.w;
            #pragma unroll
            for (int o = 16; o > 0; o >>= 1) {
                sum += __shfl_xor_sync(0xffffffffu, sum, o);
                sq  += __shfl_xor_sync(0xffffffffu, sq,  o);
            }
            float mean = sum * (1.0f/128.0f);
            float var  = sq  * (1.0f/128.0f) - mean * mean;
            float r = rsqrtf(var + 1e-5f);
            float o0 = (v.x - mean) * r * sc4.x + bc4.x;
            float o1 = (v.y - mean) * r * sc4.y + bc4.y;
            float o2 = (v.z - mean) * r * sc4.z + bc4.z;
            float o3 = (v.w - mean) * r * sc4.w + bc4.w;
            __half2* d = (__half2*)(smc + (lane >> 3) * CHB + row * SMSB + (lane & 7) * 8);
            d[0] = __floats2half2_rn(o0, o1);
            d[1] = __floats2half2_rn(o2, o3);
        }
    }
    __syncthreads();

    const int lrow = (lane & 7) + ((lane >> 3) & 1) * 8;
    const int lk2  = ((lane >> 4) & 1) * 8;
    const int ra0  = (w & 3) * 32 + lrow;
    const int rb0  = (w >> 2) * 64 + lrow;

    float acc[2][8][4];
    const int nst = (N >> 7) * 4;
    for (int s = 0; s < nst; s++) {
        if (s + 1 < nst) {
            loadB(s + 1);
            asm volatile("cp.async.wait_group 1;\n" ::);
        } else {
            asm volatile("cp.async.wait_group 0;\n" ::);
        }
        __syncthreads();
        if ((s & 3) == 0) {
            #pragma unroll
            for (int mi = 0; mi < 2; mi++)
                #pragma unroll
                for (int ni = 0; ni < 8; ni++)
                    #pragma unroll
                    for (int r = 0; r < 4; r++) acc[mi][ni][r] = 0.0f;
        }
        mma_tile16(sA + (uint32_t)((s & 3)*CHB), sB + (uint32_t)((s & 1)*CHB),
                   ra0, rb0, lk2, acc);
        if ((s & 3) == 3)
            epi12816<EPI, OUT16>(acc, bias, nullptr, C, M, N, bm, (s >> 2) * 128,
                                 w & 3, w >> 2, lane);
        __syncthreads();
    }
}

// ---------------- fused attention + o-proj (+residual): N=128, K=128, qkv fp16 ----------------
__global__ void __launch_bounds__(256, 2)
attn16(const __half* __restrict__ qkv, const __half* __restrict__ Bt,
       const float* __restrict__ bias, float* __restrict__ H, int M) {
    extern __shared__ char smc[];
    const int tid  = threadIdx.x;
    const int lane = tid & 31;
    const int w    = tid >> 5;
    const int bm   = blockIdx.y * 128;

    const uint32_t sA = (uint32_t)__cvta_generic_to_shared(smc);
    const uint32_t sB = sA + 4*CHB;

    auto loadB = [&](int kc, int buf) {
        #pragma unroll
        for (int l = 0; l < 2; l++) {
            int idx = tid + l * 256;
            int row = idx >> 2;
            int g   = idx & 3;
            cpasync16(sB + (uint32_t)(buf*CHB + row*SMSB + g*16),
                      Bt + (size_t)row * 128 + kc * 32 + g * 8, true);
        }
        cp_commit();
    };

    loadB(0, 0);

    // attention: thread owns (point, head); writes 16 fp16 per token row into A tile
    {
        int p_local = tid >> 3;
        int hh = tid & 7;
        int p = (bm >> 2) + p_local;
        if (p < NP) {
            const __half* base = qkv + (size_t)p * 1536 + hh * 16;
            #pragma unroll
            for (int qi = 0; qi < 4; qi++) {
                float q[16];
                ld16h(base + qi * 384, q);
                float sc[4];
                float mx = -1e30f;
                #pragma unroll
                for (int ki = 0; ki < 4; ki++) {
                    float kv[16];
                    ld16h(base + 128 + ki * 384, kv);
                    float s = 0.0f;
                    #pragma unroll
                    for (int c = 0; c < 16; c++) s += q[c] * kv[c];
                    s *= 0.25f;
                    sc[ki] = s;
                    mx = fmaxf(mx, s);
                }
                float sum = 0.0f;
                #pragma unroll
                for (int ki = 0; ki < 4; ki++) { sc[ki] = expf(sc[ki] - mx); sum += sc[ki]; }
                float inv = 1.0f / sum;
                float acco[16];
                #pragma unroll
                for (int d = 0; d < 16; d++) acco[d] = 0.0f;
                #pragma unroll
                for (int ki = 0; ki < 4; ki++) {
                    float wv = sc[ki] * inv;
                    float vv[16];
                    ld16h(base + 256 + ki * 384, vv);
                    #pragma unroll
                    for (int c = 0; c < 16; c++) acco[c] += wv * vv[c];
                }
                int row = p_local * 4 + qi;
                __half2* d = (__half2*)(smc + (hh >> 1) * CHB + row * SMSB + (hh & 1) * 32);
                #pragma unroll
                for (int c = 0; c < 8; c++)
                    d[c] = __floats2half2_rn(acco[2*c], acco[2*c+1]);
            }
        } else {
            int p_l = tid >> 3, hh2 = tid & 7;
            #pragma unroll
            for (int qi = 0; qi < 4; qi++) {
                int row = p_l * 4 + qi;
                __half2* d = (__half2*)(smc + (hh2 >> 1) * CHB + row * SMSB + (hh2 & 1) * 32);
                #pragma unroll
                for (int c = 0; c < 8; c++) d[c] = __floats2half2_rn(0.0f, 0.0f);
            }
        }
    }

    float acc[2][8][4];
    #pragma unroll
    for (int mi = 0; mi < 2; mi++)
        #pragma unroll
        for (int ni = 0; ni < 8; ni++)
            #pragma unroll
            for (int r = 0; r < 4; r++) acc[mi][ni][r] = 0.0f;

    const int lrow = (lane & 7) + ((lane >> 3) & 1) * 8;
    const int lk2  = ((lane >> 4) & 1) * 8;
    const int ra0  = (w & 3) * 32 + lrow;
    const int rb0  = (w >> 2) * 64 + lrow;

    for (int kc = 0; kc < 4; kc++) {
        if (kc < 3) {
            loadB(kc + 1, (kc + 1) & 1);
            asm volatile("cp.async.wait_group 1;\n" ::);
        } else {
            asm volatile("cp.async.wait_group 0;\n" ::);
        }
        __syncthreads();
        mma_tile16(sA + (uint32_t)(kc*CHB), sB + (uint32_t)((kc & 1)*CHB),
                   ra0, rb0, lk2, acc);
        __syncthreads();
    }
    epi12816<1, false>(acc, bias, H, H, M, 128, bm, 0, w & 3, w >> 2, lane);
}

// ---------------- output init + final divide ----------------
__global__ void zero_kernel(float* __restrict__ out) {
    int i = blockIdx.x * blockDim.x + threadIdx.x;
    if (i < NCELL * CLN) out[i] = 0.0f;
    else if (i < NCELL * CLN + NCELL) g_cnt[i - NCELL * CLN] = 0.0f;
}

__global__ void div_kernel(float* __restrict__ out) {
    int i = blockIdx.x * blockDim.x + threadIdx.x;
    if (i >= NCELL * 512) return;
    out[i] *= 1.0f / fmaxf(g_cnt[i >> 9], 1.0f);
}

// ---------------- driver ----------------
extern "C" void kernel_launch(void* const* d_in, const int* in_sizes, int n_in,
                              void* d_out, int out_size) {
    const float* x      = (const float*)d_in[0];
    const float* W_emb  = (const float*)d_in[1];
    const float* b_emb  = (const float*)d_in[2];
    const float* ln1_s  = (const float*)d_in[3];
    const float* ln1_b  = (const float*)d_in[4];
    const float* Wqkv   = (const float*)d_in[5];
    const float* bqkv   = (const float*)d_in[6];
    const float* Wo     = (const float*)d_in[7];
    const float* bo     = (const float*)d_in[8];
    const float* ln2_s  = (const float*)d_in[9];
    const float* ln2_b  = (const float*)d_in[10];
    const float* Wf1    = (const float*)d_in[11];
    const float* bf1    = (const float*)d_in[12];
    const float* Wf2    = (const float*)d_in[13];
    const float* bf2    = (const float*)d_in[14];
    const float* W_comb = (const float*)d_in[15];
    const float* b_comb = (const float*)d_in[16];
    float* out = (float*)d_out;

    float *p_h;
    __half *p_feat, *p_h16, *p_qkv, *p_gel, *p_wt;
    cudaGetSymbolAddress((void**)&p_feat, g_feat);
    cudaGetSymbolAddress((void**)&p_h,    g_h);
    cudaGetSymbolAddress((void**)&p_h16,  g_h16);
    cudaGetSymbolAddress((void**)&p_qkv,  g_qkv);
    cudaGetSymbolAddress((void**)&p_gel,  g_gel);
    cudaGetSymbolAddress((void**)&p_wt,   g_wt);

    const int SMEM_G = 4 * CHB;   // 40960
    const int SMEM_F = 6 * CHB;   // 61440
    static bool attr_done = false;
    if (!attr_done) {
        cudaFuncSetAttribute((const void*)gemm_tc16<0,false>, cudaFuncAttributeMaxDynamicSharedMemorySize, SMEM_G);
        cudaFuncSetAttribute((const void*)gemm_tc16<1,false>, cudaFuncAttributeMaxDynamicSharedMemorySize, SMEM_G);
        cudaFuncSetAttribute((const void*)gemm_tc16<1,true>,  cudaFuncAttributeMaxDynamicSharedMemorySize, SMEM_G);
        cudaFuncSetAttribute((const void*)gemm_tc16<3,false>, cudaFuncAttributeMaxDynamicSharedMemorySize, SMEM_G);
        cudaFuncSetAttribute((const void*)lnA16<0,true>, cudaFuncAttributeMaxDynamicSharedMemorySize, SMEM_F);
        cudaFuncSetAttribute((const void*)lnA16<2,true>, cudaFuncAttributeMaxDynamicSharedMemorySize, SMEM_F);
        cudaFuncSetAttribute((const void*)attn16,        cudaFuncAttributeMaxDynamicSharedMemorySize, SMEM_F);
        attr_done = true;
    }

    const int TB = 256;

    // fp16 weight offsets in g_wt
    __half* wembT  = p_wt + 0;        // [512][96]
    __half* wqkvT0 = p_wt + 49152;    // [384][128]
    __half* wqkvT1 = p_wt + 98304;
    __half* woT0   = p_wt + 147456;   // [128][128]
    __half* woT1   = p_wt + 163840;
    __half* wf1T0  = p_wt + 180224;   // [512][128]
    __half* wf1T1  = p_wt + 245760;
    __half* wf2T0  = p_wt + 311296;   // [128][512]
    __half* wf2T1  = p_wt + 376832;
    __half* wcombT = p_wt + 442368;   // [512][512]

    wconv<<<(704512 + TB - 1) / TB, TB>>>(W_emb, Wqkv, Wo, Wf1, Wf2, W_comb);
    // zero out + counts BEFORE feat (feat accumulates counts)
    zero_kernel<<<(NCELL * CLN + NCELL + TB - 1) / TB, TB>>>(out);
    feat_kernel<<<(NP + TB - 1) / TB, TB>>>(x);

    // embedding: feat(NP x 96 fp16) @ W_emb -> h (fp32)
    gemm_tc16<0,false><<<dim3(4, (NP + 127) / 128), TB, SMEM_G>>>(
        p_feat, wembT, b_emb, nullptr, p_h, NP, 512, 96, 96, 96);

    const __half* wqkvT[2] = {wqkvT0, wqkvT1};
    const __half* woT[2]   = {woT0, woT1};
    const __half* wf1T[2]  = {wf1T0, wf1T1};
    const __half* wf2T[2]  = {wf2T0, wf2T1};
    const int MB = (NTOK + 127) / 128;   // 2048

    for (int i = 0; i < 2; i++) {
        // LN1 + QKV -> fp16 qkv
        lnA16<0,true><<<dim3(1, MB), TB, SMEM_F>>>(p_h, wqkvT[i], bqkv + i * 384,
                                                   ln1_s + i * 128, ln1_b + i * 128,
                                                   p_qkv, NTOK, 384);
        // attention + o-proj + residual
        attn16<<<dim3(1, MB), TB, SMEM_F>>>(p_qkv, woT[i], bo + i * 128, p_h, NTOK);
        // LN2 + FF1 + GELU -> g_gel (fp16)
        lnA16<2,true><<<dim3(1, MB), TB, SMEM_F>>>(p_h, wf1T[i], bf1 + i * 512,
                                                   ln2_s + i * 128, ln2_b + i * 128,
                                                   p_gel, NTOK, 512);
        // FF2 + residual; last layer also emits fp16 h for the head
        if (i == 0)
            gemm_tc16<1,false><<<dim3(1, MB), TB, SMEM_G>>>(p_gel, wf2T[i], bf2 + i * 128,
                                                            p_h, p_h, NTOK, 128, 512, 512, 512);
        else
            gemm_tc16<1,true><<<dim3(1, MB), TB, SMEM_G>>>(p_gel, wf2T[i], bf2 + i * 128,
                                                           p_h, p_h16, NTOK, 128, 512, 512, 512);
    }

    // head: h16(NP x 512) @ W_comb -> scattered directly into out (atomicAdd)
    gemm_tc16<3,false><<<dim3(4, (NP + 127) / 128), TB, SMEM_G>>>(
        p_h16, wcombT, b_comb, nullptr, out, NP, 512, 512, 512, 512);

    // final divide by counts
    div_kernel<<<(NCELL * 512 + TB - 1) / TB, TB>>>(out);
}

// round 10
// speedup vs baseline: 1.6270x; 1.0196x over previous
#include <cuda_runtime.h>
#include <cuda_fp16.h>
#include <math.h>
#include <stdint.h>

#define NP    65534
#define NTOK  (NP*4)          // 262136 tokens
#define GH    180
#define GW    360
#define NCELL (GH*GW)         // 64800
#define CLN   512

#define SMSB 80               // bytes per smem row (32 fp16 = 64B + 16B pad)
#define CHB  (128*SMSB)       // 10240 bytes per 128x32 fp16 chunk

// ---------------- scratch (device globals: no allocation allowed) ----------------
__device__ __half g_feat[(size_t)NP*96];     // 75 used + zero pad to 96 (fp16)
__device__ int    g_flat[NP];
__device__ __half g_h   [(size_t)NTOK*128];  // transformer state (fp16)
__device__ __half g_qkv [(size_t)NTOK*384];  // fp16 qkv
__device__ __half g_gel [(size_t)NTOK*512];  // gelu output (fp16)
__device__ float  g_cnt [NCELL];
__device__ __half g_wt  [704512];            // transposed fp16 weights

// ---------------- small PTX helpers ----------------
__device__ __forceinline__ void cpasync16(uint32_t dst, const void* src, bool pred) {
    int sz = pred ? 16 : 0;      // sz=0 => zero-fill 16 bytes
    asm volatile("cp.async.cg.shared.global [%0], [%1], 16, %2;\n"
                 :: "r"(dst), "l"(src), "r"(sz));
}
__device__ __forceinline__ void cp_commit() {
    asm volatile("cp.async.commit_group;\n" ::);
}
__device__ __forceinline__ void ldm4(uint32_t& r0, uint32_t& r1, uint32_t& r2, uint32_t& r3, uint32_t addr) {
    asm volatile("ldmatrix.sync.aligned.m8n8.x4.shared.b16 {%0,%1,%2,%3}, [%4];\n"
                 : "=r"(r0), "=r"(r1), "=r"(r2), "=r"(r3) : "r"(addr));
}
__device__ __forceinline__ void mma_f16(float* c, const uint32_t* a, uint32_t b0, uint32_t b1) {
    asm volatile("mma.sync.aligned.m16n8k16.row.col.f32.f16.f16.f32 "
                 "{%0,%1,%2,%3}, {%4,%5,%6,%7}, {%8,%9}, {%0,%1,%2,%3};\n"
                 : "+f"(c[0]), "+f"(c[1]), "+f"(c[2]), "+f"(c[3])
                 : "r"(a[0]), "r"(a[1]), "r"(a[2]), "r"(a[3]), "r"(b0), "r"(b1));
}
__device__ __forceinline__ float gelu_t(float u) {
    return 0.5f * u * (1.0f + tanhf(0.7978845608028654f * (u + 0.044715f * u * u * u)));
}
// load 16 fp16 -> float[16] (two 16B vector loads)
__device__ __forceinline__ void ld16h(const __half* p, float* o) {
    uint4 u0 = *(const uint4*)p;
    uint4 u1 = *(const uint4*)(p + 8);
    const uint32_t* w0 = (const uint32_t*)&u0;
    const uint32_t* w1 = (const uint32_t*)&u1;
    #pragma unroll
    for (int i = 0; i < 4; i++) {
        float2 f = __half22float2(*(const __half2*)&w0[i]);
        o[2*i+0] = f.x; o[2*i+1] = f.y;
    }
    #pragma unroll
    for (int i = 0; i < 4; i++) {
        float2 f = __half22float2(*(const __half2*)&w1[i]);
        o[8+2*i+0] = f.x; o[8+2*i+1] = f.y;
    }
}

// 128x128x32 fp16 mma on one k-chunk. aBase/bBase: smem byte addr of 128x32 chunk.
__device__ __forceinline__ void mma_tile16(uint32_t aBase, uint32_t bBase,
                                           int ra0, int rb0, int lk2,
                                           float acc[2][8][4]) {
    #pragma unroll
    for (int kk = 0; kk < 32; kk += 16) {
        uint32_t a[2][4];
        #pragma unroll
        for (int mi = 0; mi < 2; mi++)
            ldm4(a[mi][0], a[mi][1], a[mi][2], a[mi][3],
                 aBase + (uint32_t)((ra0 + mi * 16) * SMSB + (kk + lk2) * 2));
        uint32_t b0[8], b1[8];
        #pragma unroll
        for (int np = 0; np < 4; np++) {
            uint32_t r0, r1, r2, r3;
            ldm4(r0, r1, r2, r3,
                 bBase + (uint32_t)((rb0 + np * 16) * SMSB + (kk + lk2) * 2));
            b0[2*np] = r0; b0[2*np+1] = r1;
            b1[2*np] = r2; b1[2*np+1] = r3;
        }
        #pragma unroll
        for (int mi = 0; mi < 2; mi++)
            #pragma unroll
            for (int ni = 0; ni < 8; ni++)
                mma_f16(acc[mi][ni], a[mi], b0[ni], b1[ni]);
    }
}

// epilogue for 128-row tiles, warp layout 4x2 (warp tile 32x64)
// EPI: 0=bias->C, 1=bias+fp16residual->C, 2=bias+gelu->C, 3=bias+grid-scatter(atomicAdd fp32)
// OUT16: C is fp16 (ignored for EPI==3). R (EPI==1) is fp16.
template<int EPI, bool OUT16>
__device__ __forceinline__ void epi12816(float acc[2][8][4], const float* __restrict__ bias,
                                         const void* __restrict__ R, void* __restrict__ C,
                                         int M, int N, int bm, int bn, int wm, int wn, int lane) {
    const int row0 = bm + wm * 32 + (lane >> 2);
    const int col0 = bn + wn * 64 + (lane & 3) * 2;
    #pragma unroll
    for (int mi = 0; mi < 2; mi++) {
        #pragma unroll
        for (int half = 0; half < 2; half++) {
            int gm = row0 + mi * 16 + half * 8;
            if (gm >= M) continue;
            int cell = (EPI == 3) ? g_flat[gm] : 0;
            #pragma unroll
            for (int ni = 0; ni < 8; ni++) {
                int gn = col0 + ni * 8;
                float v0 = acc[mi][ni][half*2 + 0] + bias[gn];
                float v1 = acc[mi][ni][half*2 + 1] + bias[gn + 1];
                if (EPI == 1) {
                    __half2 rh = *(const __half2*)((const __half*)R + (size_t)gm * N + gn);
                    float2 rf = __half22float2(rh);
                    v0 += rf.x; v1 += rf.y;
                }
                if (EPI == 2) { v0 = gelu_t(v0); v1 = gelu_t(v1); }
                if (EPI == 3) {
                    float* dst = (float*)C + (size_t)cell * CLN + gn;
                    atomicAdd(dst,     v0);
                    atomicAdd(dst + 1, v1);
                } else if (OUT16) {
                    *(__half2*)((__half*)C + (size_t)gm * N + gn) = __floats2half2_rn(v0, v1);
                } else {
                    float2 o; o.x = v0; o.y = v1;
                    *(float2*)((float*)C + (size_t)gm * N + gn) = o;
                }
            }
        }
    }
}

// ---------------- feature build + grid index + counts (fp16 output) ----------------
__global__ void feat_kernel(const float* __restrict__ x) {
    int i = blockIdx.x * blockDim.x + threadIdx.x;
    if (i >= NP) return;
    const float* xr = x + (size_t)i * 24;
    float lat = xr[0];
    if (lat == -90.0f) lat += 0.0001f;
    float lon = xr[1];
    float t   = xr[2];

    int lati = (int)floorf(90.0f - lat);
    int loni = (int)fmodf(180.0f + floorf(lon + 180.0f), 360.0f);
    int cell = lati * GW + loni;
    g_flat[i] = cell;
    atomicAdd(&g_cnt[cell], 1.0f);

    __half* f = g_feat + (size_t)i * 96;
    f[0] = __float2half_rn(lat * (1.0f/90.0f));
    f[1] = __float2half_rn(lon * (1.0f/180.0f));
    f[2] = __float2half_rn(t   * (1.0f/12.0f));
    #pragma unroll
    for (int j = 3; j < 24; j++) f[j] = __float2half_rn(xr[j]);

    float p0 = -lat - floorf(-lat);
    float p1 =  lon - floorf(lon);
    float p2 =  t + 1.0f;
    f[24] = __float2half_rn(p0); f[25] = __float2half_rn(p1); f[26] = __float2half_rn(p2);
    float p[3] = {p0, p1, p2};
    #pragma unroll
    for (int c = 0; c < 3; c++) {
        float fr = 3.14159274101257324f;
        #pragma unroll
        for (int k = 0; k < 8; k++) {
            float ang = p[c] * fr;
            f[27 + c*8 + k] = __float2half_rn(sinf(ang));
            f[51 + c*8 + k] = __float2half_rn(cosf(ang));
            fr *= 2.0f;
        }
    }
    #pragma unroll
    for (int j = 75; j < 96; j++) f[j] = __float2half_rn(0.0f);
}

// ---------------- all-in-one weight transpose + fp16 round ----------------
__global__ void wconv(const float* __restrict__ W_emb, const float* __restrict__ Wqkv,
                      const float* __restrict__ Wo, const float* __restrict__ Wf1,
                      const float* __restrict__ Wf2, const float* __restrict__ W_comb) {
    int idx = blockIdx.x * blockDim.x + threadIdx.x;
    if (idx >= 704512) return;
    const float* srcs[6] = {W_emb, Wqkv, Wo, Wf1, Wf2, W_comb};
    const int sel [10] = {0,1,1,2,2,3,3,4,4,5};
    const int soff[10] = {0,0,49152,0,16384,0,65536,0,65536,0};
    const int Kt  [10] = {75,128,128,128,128,128,128,512,512,512};
    const int Nt  [10] = {512,384,384,128,128,512,512,128,128,512};
    const int Kp  [10] = {96,128,128,128,128,128,128,512,512,512};
    const int dst [10] = {0,49152,98304,147456,163840,180224,245760,311296,376832,442368};
    int m = 0;
    #pragma unroll
    for (int i = 1; i < 10; i++) if (idx >= dst[i]) m = i;
    int local = idx - dst[m];
    int n = local / Kp[m];
    int k = local - n * Kp[m];
    float v = (k < Kt[m]) ? srcs[sel[m]][soff[m] + (size_t)k * Nt[m] + n] : 0.0f;
    g_wt[idx] = __float2half_rn(v);
}

// ---------------- generic fp16 GEMM (emb K=96, ff2 K=512, head K=512) ----------------
template<int EPI, bool OUT16>
__global__ void __launch_bounds__(256, 2)
gemm_tc16(const __half* __restrict__ A, const __half* __restrict__ Bt,
          const float* __restrict__ bias, const void* __restrict__ R,
          void* __restrict__ C, int M, int N, int K, int lda, int ldb) {
    extern __shared__ char smc[];
    const int tid  = threadIdx.x;
    const int lane = tid & 31;
    const int w    = tid >> 5;
    const int wm   = w & 3;
    const int wn   = w >> 2;
    const int bm   = blockIdx.y * 128;
    const int bn   = blockIdx.x * 128;

    const uint32_t sA = (uint32_t)__cvta_generic_to_shared(smc);
    const uint32_t sB = sA + 2*CHB;

    float acc[2][8][4];
    #pragma unroll
    for (int mi = 0; mi < 2; mi++)
        #pragma unroll
        for (int ni = 0; ni < 8; ni++)
            #pragma unroll
            for (int r = 0; r < 4; r++) acc[mi][ni][r] = 0.0f;

    const int lrow = (lane & 7) + ((lane >> 3) & 1) * 8;
    const int lk2  = ((lane >> 4) & 1) * 8;
    const int ra0  = wm * 32 + lrow;
    const int rb0  = wn * 64 + lrow;
    const int niter = K >> 5;

    auto load_stage = [&](int s, int k0) {
        #pragma unroll
        for (int l = 0; l < 2; l++) {
            int idx = tid + l * 256;      // 0..511
            int row = idx >> 2;
            int g   = idx & 3;
            bool pa = (bm + row) < M;
            const void* src = pa ? (const void*)(A + (size_t)(bm + row) * lda + k0 + g * 8)
                                 : (const void*)A;
            cpasync16(sA + (uint32_t)(s*CHB + row*SMSB + g*16), src, pa);
        }
        #pragma unroll
        for (int l = 0; l < 2; l++) {
            int idx = tid + l * 256;
            int row = idx >> 2;
            int g   = idx & 3;
            cpasync16(sB + (uint32_t)(s*CHB + row*SMSB + g*16),
                      Bt + (size_t)(bn + row) * ldb + k0 + g * 8, true);
        }
        cp_commit();
    };

    load_stage(0, 0);
    for (int it = 0; it < niter; it++) {
        if (it + 1 < niter) {
            load_stage((it + 1) & 1, (it + 1) * 32);
            asm volatile("cp.async.wait_group 1;\n" ::);
        } else {
            asm volatile("cp.async.wait_group 0;\n" ::);
        }
        __syncthreads();
        const int s = it & 1;
        mma_tile16(sA + (uint32_t)(s*CHB), sB + (uint32_t)(s*CHB), ra0, rb0, lk2, acc);
        __syncthreads();
    }
    epi12816<EPI, OUT16>(acc, bias, R, C, M, N, bm, bn, wm, wn, lane);
}

// ---------------- fused LN + GEMM over all n-blocks (A resident fp16): K=128 ----------------
// grid (1, M/128). H is fp16. EPI=0 -> qkv fp16 (N=384). EPI=2 -> gel fp16 (N=512).
template<int EPI>
__global__ void __launch_bounds__(256, 2)
lnA16(const __half* __restrict__ H, const __half* __restrict__ Bt,
      const float* __restrict__ bias, const float* __restrict__ lns,
      const float* __restrict__ lnb, void* __restrict__ C, int M, int N) {
    extern __shared__ char smc[];
    const int tid  = threadIdx.x;
    const int lane = tid & 31;
    const int w    = tid >> 5;
    const int bm   = blockIdx.y * 128;

    const uint32_t sA = (uint32_t)__cvta_generic_to_shared(smc);
    const uint32_t sB = sA + 4*CHB;

    auto loadB = [&](int s) {
        int nb = s >> 2, kc = s & 3, buf = s & 1;
        #pragma unroll
        for (int l = 0; l < 2; l++) {
            int idx = tid + l * 256;
            int row = idx >> 2;
            int g   = idx & 3;
            cpasync16(sB + (uint32_t)(buf*CHB + row*SMSB + g*16),
                      Bt + (size_t)(nb * 128 + row) * 128 + kc * 32 + g * 8, true);
        }
        cp_commit();
    };

    loadB(0);

    // LayerNorm: warp w rows w*16..+15; lane covers k = lane*4..+3; h fp16 in, fp16 smem out
    {
        const float4 sc4 = ((const float4*)lns)[lane];
        const float4 bc4 = ((const float4*)lnb)[lane];
        #pragma unroll
        for (int rr = 0; rr < 16; rr++) {
            int row = w * 16 + rr;
            int gm  = bm + row;
            float v0 = 0.0f, v1 = 0.0f, v2 = 0.0f, v3 = 0.0f;
            if (gm < M) {
                uint2 u = *(const uint2*)(H + (size_t)gm * 128 + lane * 4);
                float2 fa = __half22float2(*(const __half2*)&u.x);
                float2 fb = __half22float2(*(const __half2*)&u.y);
                v0 = fa.x; v1 = fa.y; v2 = fb.x; v3 = fb.y;
            }
            float sum = v0 + v1 + v2 + v3;
            float sq  = v0*v0 + v1*v1 + v2*v2 + v3*v3;
            #pragma unroll
            for (int o = 16; o > 0; o >>= 1) {
                sum += __shfl_xor_sync(0xffffffffu, sum, o);
                sq  += __shfl_xor_sync(0xffffffffu, sq,  o);
            }
            float mean = sum * (1.0f/128.0f);
            float var  = sq  * (1.0f/128.0f) - mean * mean;
            float r = rsqrtf(var + 1e-5f);
            float o0 = (v0 - mean) * r * sc4.x + bc4.x;
            float o1 = (v1 - mean) * r * sc4.y + bc4.y;
            float o2 = (v2 - mean) * r * sc4.z + bc4.z;
            float o3 = (v3 - mean) * r * sc4.w + bc4.w;
            __half2* d = (__half2*)(smc + (lane >> 3) * CHB + row * SMSB + (lane & 7) * 8);
            d[0] = __floats2half2_rn(o0, o1);
            d[1] = __floats2half2_rn(o2, o3);
        }
    }
    __syncthreads();

    const int lrow = (lane & 7) + ((lane >> 3) & 1) * 8;
    const int lk2  = ((lane >> 4) & 1) * 8;
    const int ra0  = (w & 3) * 32 + lrow;
    const int rb0  = (w >> 2) * 64 + lrow;

    float acc[2][8][4];
    const int nst = (N >> 7) * 4;
    for (int s = 0; s < nst; s++) {
        if (s + 1 < nst) {
            loadB(s + 1);
            asm volatile("cp.async.wait_group 1;\n" ::);
        } else {
            asm volatile("cp.async.wait_group 0;\n" ::);
        }
        __syncthreads();
        if ((s & 3) == 0) {
            #pragma unroll
            for (int mi = 0; mi < 2; mi++)
                #pragma unroll
                for (int ni = 0; ni < 8; ni++)
                    #pragma unroll
                    for (int r = 0; r < 4; r++) acc[mi][ni][r] = 0.0f;
        }
        mma_tile16(sA + (uint32_t)((s & 3)*CHB), sB + (uint32_t)((s & 1)*CHB),
                   ra0, rb0, lk2, acc);
        if ((s & 3) == 3)
            epi12816<EPI, true>(acc, bias, nullptr, C, M, N, bm, (s >> 2) * 128,
                                w & 3, w >> 2, lane);
        __syncthreads();
    }
}

// ---------------- fused attention + o-proj (+fp16 residual): N=128, K=128 ----------------
__global__ void __launch_bounds__(256, 2)
attn16(const __half* __restrict__ qkv, const __half* __restrict__ Bt,
       const float* __restrict__ bias, __half* __restrict__ H, int M) {
    extern __shared__ char smc[];
    const int tid  = threadIdx.x;
    const int lane = tid & 31;
    const int w    = tid >> 5;
    const int bm   = blockIdx.y * 128;

    const uint32_t sA = (uint32_t)__cvta_generic_to_shared(smc);
    const uint32_t sB = sA + 4*CHB;

    auto loadB = [&](int kc, int buf) {
        #pragma unroll
        for (int l = 0; l < 2; l++) {
            int idx = tid + l * 256;
            int row = idx >> 2;
            int g   = idx & 3;
            cpasync16(sB + (uint32_t)(buf*CHB + row*SMSB + g*16),
                      Bt + (size_t)row * 128 + kc * 32 + g * 8, true);
        }
        cp_commit();
    };

    loadB(0, 0);

    // attention: thread owns (point, head); writes 16 fp16 per token row into A tile
    {
        int p_local = tid >> 3;
        int hh = tid & 7;
        int p = (bm >> 2) + p_local;
        if (p < NP) {
            const __half* base = qkv + (size_t)p * 1536 + hh * 16;
            #pragma unroll
            for (int qi = 0; qi < 4; qi++) {
                float q[16];
                ld16h(base + qi * 384, q);
                float sc[4];
                float mx = -1e30f;
                #pragma unroll
                for (int ki = 0; ki < 4; ki++) {
                    float kv[16];
                    ld16h(base + 128 + ki * 384, kv);
                    float s = 0.0f;
                    #pragma unroll
                    for (int c = 0; c < 16; c++) s += q[c] * kv[c];
                    s *= 0.25f;
                    sc[ki] = s;
                    mx = fmaxf(mx, s);
                }
                float sum = 0.0f;
                #pragma unroll
                for (int ki = 0; ki < 4; ki++) { sc[ki] = expf(sc[ki] - mx); sum += sc[ki]; }
                float inv = 1.0f / sum;
                float acco[16];
                #pragma unroll
                for (int d = 0; d < 16; d++) acco[d] = 0.0f;
                #pragma unroll
                for (int ki = 0; ki < 4; ki++) {
                    float wv = sc[ki] * inv;
                    float vv[16];
                    ld16h(base + 256 + ki * 384, vv);
                    #pragma unroll
                    for (int c = 0; c < 16; c++) acco[c] += wv * vv[c];
                }
                int row = p_local * 4 + qi;
                __half2* d = (__half2*)(smc + (hh >> 1) * CHB + row * SMSB + (hh & 1) * 32);
                #pragma unroll
                for (int c = 0; c < 8; c++)
                    d[c] = __floats2half2_rn(acco[2*c], acco[2*c+1]);
            }
        } else {
            int p_l = tid >> 3, hh2 = tid & 7;
            #pragma unroll
            for (int qi = 0; qi < 4; qi++) {
                int row = p_l * 4 + qi;
                __half2* d = (__half2*)(smc + (hh2 >> 1) * CHB + row * SMSB + (hh2 & 1) * 32);
                #pragma unroll
                for (int c = 0; c < 8; c++) d[c] = __floats2half2_rn(0.0f, 0.0f);
            }
        }
    }

    float acc[2][8][4];
    #pragma unroll
    for (int mi = 0; mi < 2; mi++)
        #pragma unroll
        for (int ni = 0; ni < 8; ni++)
            #pragma unroll
            for (int r = 0; r < 4; r++) acc[mi][ni][r] = 0.0f;

    const int lrow = (lane & 7) + ((lane >> 3) & 1) * 8;
    const int lk2  = ((lane >> 4) & 1) * 8;
    const int ra0  = (w & 3) * 32 + lrow;
    const int rb0  = (w >> 2) * 64 + lrow;

    for (int kc = 0; kc < 4; kc++) {
        if (kc < 3) {
            loadB(kc + 1, (kc + 1) & 1);
            asm volatile("cp.async.wait_group 1;\n" ::);
        } else {
            asm volatile("cp.async.wait_group 0;\n" ::);
        }
        __syncthreads();
        mma_tile16(sA + (uint32_t)(kc*CHB), sB + (uint32_t)((kc & 1)*CHB),
                   ra0, rb0, lk2, acc);
        __syncthreads();
    }
    epi12816<1, true>(acc, bias, H, H, M, 128, bm, 0, w & 3, w >> 2, lane);
}

// ---------------- output init + final divide ----------------
__global__ void zero_kernel(float* __restrict__ out) {
    int i = blockIdx.x * blockDim.x + threadIdx.x;
    if (i < NCELL * CLN) out[i] = 0.0f;
    else if (i < NCELL * CLN + NCELL) g_cnt[i - NCELL * CLN] = 0.0f;
}

__global__ void div_kernel(float* __restrict__ out) {
    int i = blockIdx.x * blockDim.x + threadIdx.x;
    if (i >= NCELL * 512) return;
    out[i] *= 1.0f / fmaxf(g_cnt[i >> 9], 1.0f);
}

// ---------------- driver ----------------
extern "C" void kernel_launch(void* const* d_in, const int* in_sizes, int n_in,
                              void* d_out, int out_size) {
    const float* x      = (const float*)d_in[0];
    const float* W_emb  = (const float*)d_in[1];
    const float* b_emb  = (const float*)d_in[2];
    const float* ln1_s  = (const float*)d_in[3];
    const float* ln1_b  = (const float*)d_in[4];
    const float* Wqkv   = (const float*)d_in[5];
    const float* bqkv   = (const float*)d_in[6];
    const float* Wo     = (const float*)d_in[7];
    const float* bo     = (const float*)d_in[8];
    const float* ln2_s  = (const float*)d_in[9];
    const float* ln2_b  = (const float*)d_in[10];
    const float* Wf1    = (const float*)d_in[11];
    const float* bf1    = (const float*)d_in[12];
    const float* Wf2    = (const float*)d_in[13];
    const float* bf2    = (const float*)d_in[14];
    const float* W_comb = (const float*)d_in[15];
    const float* b_comb = (const float*)d_in[16];
    float* out = (float*)d_out;

    __half *p_feat, *p_h, *p_qkv, *p_gel, *p_wt;
    cudaGetSymbolAddress((void**)&p_feat, g_feat);
    cudaGetSymbolAddress((void**)&p_h,    g_h);
    cudaGetSymbolAddress((void**)&p_qkv,  g_qkv);
    cudaGetSymbolAddress((void**)&p_gel,  g_gel);
    cudaGetSymbolAddress((void**)&p_wt,   g_wt);

    const int SMEM_G = 4 * CHB;   // 40960
    const int SMEM_F = 6 * CHB;   // 61440
    static bool attr_done = false;
    if (!attr_done) {
        cudaFuncSetAttribute((const void*)gemm_tc16<0,true>,  cudaFuncAttributeMaxDynamicSharedMemorySize, SMEM_G);
        cudaFuncSetAttribute((const void*)gemm_tc16<1,true>,  cudaFuncAttributeMaxDynamicSharedMemorySize, SMEM_G);
        cudaFuncSetAttribute((const void*)gemm_tc16<3,false>, cudaFuncAttributeMaxDynamicSharedMemorySize, SMEM_G);
        cudaFuncSetAttribute((const void*)lnA16<0>, cudaFuncAttributeMaxDynamicSharedMemorySize, SMEM_F);
        cudaFuncSetAttribute((const void*)lnA16<2>, cudaFuncAttributeMaxDynamicSharedMemorySize, SMEM_F);
        cudaFuncSetAttribute((const void*)attn16,   cudaFuncAttributeMaxDynamicSharedMemorySize, SMEM_F);
        attr_done = true;
    }

    const int TB = 256;

    // fp16 weight offsets in g_wt
    __half* wembT  = p_wt + 0;        // [512][96]
    __half* wqkvT0 = p_wt + 49152;    // [384][128]
    __half* wqkvT1 = p_wt + 98304;
    __half* woT0   = p_wt + 147456;   // [128][128]
    __half* woT1   = p_wt + 163840;
    __half* wf1T0  = p_wt + 180224;   // [512][128]
    __half* wf1T1  = p_wt + 245760;
    __half* wf2T0  = p_wt + 311296;   // [128][512]
    __half* wf2T1  = p_wt + 376832;
    __half* wcombT = p_wt + 442368;   // [512][512]

    wconv<<<(704512 + TB - 1) / TB, TB>>>(W_emb, Wqkv, Wo, Wf1, Wf2, W_comb);
    // zero out + counts BEFORE feat (feat accumulates counts)
    zero_kernel<<<(NCELL * CLN + NCELL + TB - 1) / TB, TB>>>(out);
    feat_kernel<<<(NP + TB - 1) / TB, TB>>>(x);

    // embedding: feat(NP x 96 fp16) @ W_emb -> h (fp16)
    gemm_tc16<0,true><<<dim3(4, (NP + 127) / 128), TB, SMEM_G>>>(
        p_feat, wembT, b_emb, nullptr, p_h, NP, 512, 96, 96, 96);

    const __half* wqkvT[2] = {wqkvT0, wqkvT1};
    const __half* woT[2]   = {woT0, woT1};
    const __half* wf1T[2]  = {wf1T0, wf1T1};
    const __half* wf2T[2]  = {wf2T0, wf2T1};
    const int MB = (NTOK + 127) / 128;   // 2048

    for (int i = 0; i < 2; i++) {
        // LN1 + QKV -> fp16 qkv
        lnA16<0><<<dim3(1, MB), TB, SMEM_F>>>(p_h, wqkvT[i], bqkv + i * 384,
                                              ln1_s + i * 128, ln1_b + i * 128,
                                              p_qkv, NTOK, 384);
        // attention + o-proj + residual (h fp16)
        attn16<<<dim3(1, MB), TB, SMEM_F>>>(p_qkv, woT[i], bo + i * 128, p_h, NTOK);
        // LN2 + FF1 + GELU -> g_gel (fp16)
        lnA16<2><<<dim3(1, MB), TB, SMEM_F>>>(p_h, wf1T[i], bf1 + i * 512,
                                              ln2_s + i * 128, ln2_b + i * 128,
                                              p_gel, NTOK, 512);
        // FF2 + residual (h fp16)
        gemm_tc16<1,true><<<dim3(1, MB), TB, SMEM_G>>>(p_gel, wf2T[i], bf2 + i * 128,
                                                       p_h, p_h, NTOK, 128, 512, 512, 512);
    }

    // head: h(NP x 512 fp16) @ W_comb -> scattered directly into out (atomicAdd)
    gemm_tc16<3,false><<<dim3(4, (NP + 127) / 128), TB, SMEM_G>>>(
        p_h, wcombT, b_comb, nullptr, out, NP, 512, 512, 512, 512);

    // final divide by counts
    div_kernel<<<(NCELL * 512 + TB - 1) / TB, TB>>>(out);
}

// round 12
// speedup vs baseline: 1.7832x; 1.0960x over previous
#include <cuda_runtime.h>
#include <cuda_fp16.h>
#include <math.h>
#include <stdint.h>

#define NP    65534
#define NTOK  (NP*4)          // 262136 tokens
#define GH    180
#define GW    360
#define NCELL (GH*GW)         // 64800
#define CLN   512

#define SMSB 80               // bytes per smem row (32 fp16 = 64B + 16B pad)
#define CHB  (128*SMSB)       // 10240 bytes per 128x32 fp16 chunk

// ---------------- scratch (device globals: no allocation allowed) ----------------
__device__ __half g_feat[(size_t)NP*96];     // 75 used + zero pad to 96 (fp16)
__device__ int    g_flat[NP];
__device__ __half g_h   [(size_t)NTOK*128];  // transformer state (fp16)
__device__ __half g_qkv [(size_t)NTOK*384];  // fp16 qkv
__device__ __half g_gel [(size_t)NTOK*512];  // gelu output (fp16)
__device__ float  g_cnt [NCELL];
__device__ __half g_wt  [704512];            // transposed fp16 weights

// ---------------- small PTX helpers ----------------
__device__ __forceinline__ void cpasync16(uint32_t dst, const void* src, bool pred) {
    int sz = pred ? 16 : 0;      // sz=0 => zero-fill 16 bytes
    asm volatile("cp.async.cg.shared.global [%0], [%1], 16, %2;\n"
                 :: "r"(dst), "l"(src), "r"(sz));
}
__device__ __forceinline__ void cp_commit() {
    asm volatile("cp.async.commit_group;\n" ::);
}
__device__ __forceinline__ void ldm4(uint32_t& r0, uint32_t& r1, uint32_t& r2, uint32_t& r3, uint32_t addr) {
    asm volatile("ldmatrix.sync.aligned.m8n8.x4.shared.b16 {%0,%1,%2,%3}, [%4];\n"
                 : "=r"(r0), "=r"(r1), "=r"(r2), "=r"(r3) : "r"(addr));
}
__device__ __forceinline__ void mma_f16(float* c, const uint32_t* a, uint32_t b0, uint32_t b1) {
    asm volatile("mma.sync.aligned.m16n8k16.row.col.f32.f16.f16.f32 "
                 "{%0,%1,%2,%3}, {%4,%5,%6,%7}, {%8,%9}, {%0,%1,%2,%3};\n"
                 : "+f"(c[0]), "+f"(c[1]), "+f"(c[2]), "+f"(c[3])
                 : "r"(a[0]), "r"(a[1]), "r"(a[2]), "r"(a[3]), "r"(b0), "r"(b1));
}
__device__ __forceinline__ float gelu_t(float u) {
    return 0.5f * u * (1.0f + tanhf(0.7978845608028654f * (u + 0.044715f * u * u * u)));
}
// load 16 fp16 -> float[16] (two 16B vector loads)
__device__ __forceinline__ void ld16h(const __half* p, float* o) {
    uint4 u0 = *(const uint4*)p;
    uint4 u1 = *(const uint4*)(p + 8);
    const uint32_t* w0 = (const uint32_t*)&u0;
    const uint32_t* w1 = (const uint32_t*)&u1;
    #pragma unroll
    for (int i = 0; i < 4; i++) {
        float2 f = __half22float2(*(const __half2*)&w0[i]);
        o[2*i+0] = f.x; o[2*i+1] = f.y;
    }
    #pragma unroll
    for (int i = 0; i < 4; i++) {
        float2 f = __half22float2(*(const __half2*)&w1[i]);
        o[8+2*i+0] = f.x; o[8+2*i+1] = f.y;
    }
}

// 128x128x32 fp16 mma on one k-chunk. aBase/bBase: smem byte addr of 128x32 chunk.
__device__ __forceinline__ void mma_tile16(uint32_t aBase, uint32_t bBase,
                                           int ra0, int rb0, int lk2,
                                           float acc[2][8][4]) {
    #pragma unroll
    for (int kk = 0; kk < 32; kk += 16) {
        uint32_t a[2][4];
        #pragma unroll
        for (int mi = 0; mi < 2; mi++)
            ldm4(a[mi][0], a[mi][1], a[mi][2], a[mi][3],
                 aBase + (uint32_t)((ra0 + mi * 16) * SMSB + (kk + lk2) * 2));
        uint32_t b0[8], b1[8];
        #pragma unroll
        for (int np = 0; np < 4; np++) {
            uint32_t r0, r1, r2, r3;
            ldm4(r0, r1, r2, r3,
                 bBase + (uint32_t)((rb0 + np * 16) * SMSB + (kk + lk2) * 2));
            b0[2*np] = r0; b0[2*np+1] = r1;
            b1[2*np] = r2; b1[2*np+1] = r3;
        }
        #pragma unroll
        for (int mi = 0; mi < 2; mi++)
            #pragma unroll
            for (int ni = 0; ni < 8; ni++)
                mma_f16(acc[mi][ni], a[mi], b0[ni], b1[ni]);
    }
}

// epilogue for 128-row tiles, warp layout 4x2 (warp tile 32x64)
// EPI: 0=bias->C, 1=bias+fp16residual->C, 2=bias+gelu->C, 3=bias+grid-scatter(atomicAdd fp32)
template<int EPI, bool OUT16>
__device__ __forceinline__ void epi12816(float acc[2][8][4], const float* __restrict__ bias,
                                         const void* __restrict__ R, void* __restrict__ C,
                                         int M, int N, int bm, int bn, int wm, int wn, int lane) {
    const int row0 = bm + wm * 32 + (lane >> 2);
    const int col0 = bn + wn * 64 + (lane & 3) * 2;
    #pragma unroll
    for (int mi = 0; mi < 2; mi++) {
        #pragma unroll
        for (int half = 0; half < 2; half++) {
            int gm = row0 + mi * 16 + half * 8;
            if (gm >= M) continue;
            int cell = (EPI == 3) ? g_flat[gm] : 0;
            #pragma unroll
            for (int ni = 0; ni < 8; ni++) {
                int gn = col0 + ni * 8;
                float v0 = acc[mi][ni][half*2 + 0] + bias[gn];
                float v1 = acc[mi][ni][half*2 + 1] + bias[gn + 1];
                if (EPI == 1) {
                    __half2 rh = *(const __half2*)((const __half*)R + (size_t)gm * N + gn);
                    float2 rf = __half22float2(rh);
                    v0 += rf.x; v1 += rf.y;
                }
                if (EPI == 2) { v0 = gelu_t(v0); v1 = gelu_t(v1); }
                if (EPI == 3) {
                    float* dst = (float*)C + (size_t)cell * CLN + gn;
                    atomicAdd(dst,     v0);
                    atomicAdd(dst + 1, v1);
                } else if (OUT16) {
                    *(__half2*)((__half*)C + (size_t)gm * N + gn) = __floats2half2_rn(v0, v1);
                } else {
                    float2 o; o.x = v0; o.y = v1;
                    *(float2*)((float*)C + (size_t)gm * N + gn) = o;
                }
            }
        }
    }
}

// ---------------- feature build + grid index + counts (fp16 output) ----------------
__global__ void feat_kernel(const float* __restrict__ x) {
    int i = blockIdx.x * blockDim.x + threadIdx.x;
    if (i >= NP) return;
    const float* xr = x + (size_t)i * 24;
    float lat = xr[0];
    if (lat == -90.0f) lat += 0.0001f;
    float lon = xr[1];
    float t   = xr[2];

    int lati = (int)floorf(90.0f - lat);
    int loni = (int)fmodf(180.0f + floorf(lon + 180.0f), 360.0f);
    int cell = lati * GW + loni;
    g_flat[i] = cell;
    atomicAdd(&g_cnt[cell], 1.0f);

    __half* f = g_feat + (size_t)i * 96;
    f[0] = __float2half_rn(lat * (1.0f/90.0f));
    f[1] = __float2half_rn(lon * (1.0f/180.0f));
    f[2] = __float2half_rn(t   * (1.0f/12.0f));
    #pragma unroll
    for (int j = 3; j < 24; j++) f[j] = __float2half_rn(xr[j]);

    float p0 = -lat - floorf(-lat);
    float p1 =  lon - floorf(lon);
    float p2 =  t + 1.0f;
    f[24] = __float2half_rn(p0); f[25] = __float2half_rn(p1); f[26] = __float2half_rn(p2);
    float p[3] = {p0, p1, p2};
    #pragma unroll
    for (int c = 0; c < 3; c++) {
        float fr = 3.14159274101257324f;
        #pragma unroll
        for (int k = 0; k < 8; k++) {
            float ang = p[c] * fr;
            f[27 + c*8 + k] = __float2half_rn(sinf(ang));
            f[51 + c*8 + k] = __float2half_rn(cosf(ang));
            fr *= 2.0f;
        }
    }
    #pragma unroll
    for (int j = 75; j < 96; j++) f[j] = __float2half_rn(0.0f);
}

// ---------------- all-in-one weight transpose + fp16 round ----------------
__global__ void wconv(const float* __restrict__ W_emb, const float* __restrict__ Wqkv,
                      const float* __restrict__ Wo, const float* __restrict__ Wf1,
                      const float* __restrict__ Wf2, const float* __restrict__ W_comb) {
    int idx = blockIdx.x * blockDim.x + threadIdx.x;
    if (idx >= 704512) return;
    const float* srcs[6] = {W_emb, Wqkv, Wo, Wf1, Wf2, W_comb};
    const int sel [10] = {0,1,1,2,2,3,3,4,4,5};
    const int soff[10] = {0,0,49152,0,16384,0,65536,0,65536,0};
    const int Kt  [10] = {75,128,128,128,128,128,128,512,512,512};
    const int Nt  [10] = {512,384,384,128,128,512,512,128,128,512};
    const int Kp  [10] = {96,128,128,128,128,128,128,512,512,512};
    const int dst [10] = {0,49152,98304,147456,163840,180224,245760,311296,376832,442368};
    int m = 0;
    #pragma unroll
    for (int i = 1; i < 10; i++) if (idx >= dst[i]) m = i;
    int local = idx - dst[m];
    int n = local / Kp[m];
    int k = local - n * Kp[m];
    float v = (k < Kt[m]) ? srcs[sel[m]][soff[m] + (size_t)k * Nt[m] + n] : 0.0f;
    g_wt[idx] = __float2half_rn(v);
}

// ---------------- generic fp16 GEMM, 4-buf ring, depth-2, 1 sync/chunk ----------------
// Order per chunk: issue load(c+2) -> wait own groups -> BARRIER -> mma(c).
// Barrier AFTER wait publishes all threads' completed loads (fixes the R11 race);
// barrier also orders ring reuse: mma(c-2) of every warp precedes load(c+2) of
// every thread via the iteration-(c-1) barrier.
template<int EPI, bool OUT16>
__global__ void __launch_bounds__(256, 2)
gemm_tc16(const __half* __restrict__ A, const __half* __restrict__ Bt,
          const float* __restrict__ bias, const void* __restrict__ R,
          void* __restrict__ C, int M, int N, int K, int lda, int ldb) {
    extern __shared__ char smc[];
    const int tid  = threadIdx.x;
    const int lane = tid & 31;
    const int w    = tid >> 5;
    const int wm   = w & 3;
    const int wn   = w >> 2;
    const int bm   = blockIdx.y * 128;
    const int bn   = blockIdx.x * 128;

    const uint32_t sA = (uint32_t)__cvta_generic_to_shared(smc);
    const uint32_t sB = sA + 4*CHB;

    float acc[2][8][4];
    #pragma unroll
    for (int mi = 0; mi < 2; mi++)
        #pragma unroll
        for (int ni = 0; ni < 8; ni++)
            #pragma unroll
            for (int r = 0; r < 4; r++) acc[mi][ni][r] = 0.0f;

    const int lrow = (lane & 7) + ((lane >> 3) & 1) * 8;
    const int lk2  = ((lane >> 4) & 1) * 8;
    const int ra0  = wm * 32 + lrow;
    const int rb0  = wn * 64 + lrow;
    const int nc   = K >> 5;

    auto load_chunk = [&](int c) {
        int buf = c & 3;
        int k0  = c * 32;
        #pragma unroll
        for (int l = 0; l < 2; l++) {
            int idx = tid + l * 256;      // 0..511
            int row = idx >> 2;
            int g   = idx & 3;
            bool pa = (bm + row) < M;
            const void* src = pa ? (const void*)(A + (size_t)(bm + row) * lda + k0 + g * 8)
                                 : (const void*)A;
            cpasync16(sA + (uint32_t)(buf*CHB + row*SMSB + g*16), src, pa);
        }
        #pragma unroll
        for (int l = 0; l < 2; l++) {
            int idx = tid + l * 256;
            int row = idx >> 2;
            int g   = idx & 3;
            cpasync16(sB + (uint32_t)(buf*CHB + row*SMSB + g*16),
                      Bt + (size_t)(bn + row) * ldb + k0 + g * 8, true);
        }
        cp_commit();
    };

    load_chunk(0);
    if (nc > 1) load_chunk(1);
    for (int c = 0; c < nc; c++) {
        if (c + 2 < nc) {
            load_chunk(c + 2);
            asm volatile("cp.async.wait_group 2;\n" ::);
        } else if (c + 1 < nc) {
            asm volatile("cp.async.wait_group 1;\n" ::);
        } else {
            asm volatile("cp.async.wait_group 0;\n" ::);
        }
        __syncthreads();                          // publish chunk c + fence ring reuse
        int buf = c & 3;
        mma_tile16(sA + (uint32_t)(buf*CHB), sB + (uint32_t)(buf*CHB), ra0, rb0, lk2, acc);
    }
    epi12816<EPI, OUT16>(acc, bias, R, C, M, N, bm, bn, wm, wn, lane);
}

// ---------------- fused LN + GEMM over all n-blocks (A resident fp16): K=128 ----------------
// grid (1, M/128). H is fp16. EPI=0 -> qkv fp16 (N=384). EPI=2 -> gel fp16 (N=512).
// B: 4-buffer ring, depth-2 prefetch; sync after wait (same scheme as gemm_tc16).
template<int EPI>
__global__ void __launch_bounds__(256, 2)
lnA16(const __half* __restrict__ H, const __half* __restrict__ Bt,
      const float* __restrict__ bias, const float* __restrict__ lns,
      const float* __restrict__ lnb, void* __restrict__ C, int M, int N) {
    extern __shared__ char smc[];
    const int tid  = threadIdx.x;
    const int lane = tid & 31;
    const int w    = tid >> 5;
    const int bm   = blockIdx.y * 128;

    const uint32_t sA = (uint32_t)__cvta_generic_to_shared(smc);
    const uint32_t sB = sA + 4*CHB;

    auto loadB = [&](int s) {
        int nb = s >> 2, kc = s & 3, buf = s & 3;
        #pragma unroll
        for (int l = 0; l < 2; l++) {
            int idx = tid + l * 256;
            int row = idx >> 2;
            int g   = idx & 3;
            cpasync16(sB + (uint32_t)(buf*CHB + row*SMSB + g*16),
                      Bt + (size_t)(nb * 128 + row) * 128 + kc * 32 + g * 8, true);
        }
        cp_commit();
    };

    loadB(0);
    loadB(1);

    // LayerNorm: warp w rows w*16..+15; lane covers k = lane*4..+3; h fp16 in, fp16 smem out
    {
        const float4 sc4 = ((const float4*)lns)[lane];
        const float4 bc4 = ((const float4*)lnb)[lane];
        #pragma unroll
        for (int rr = 0; rr < 16; rr++) {
            int row = w * 16 + rr;
            int gm  = bm + row;
            float v0 = 0.0f, v1 = 0.0f, v2 = 0.0f, v3 = 0.0f;
            if (gm < M) {
                uint2 u = *(const uint2*)(H + (size_t)gm * 128 + lane * 4);
                float2 fa = __half22float2(*(const __half2*)&u.x);
                float2 fb = __half22float2(*(const __half2*)&u.y);
                v0 = fa.x; v1 = fa.y; v2 = fb.x; v3 = fb.y;
            }
            float sum = v0 + v1 + v2 + v3;
            float sq  = v0*v0 + v1*v1 + v2*v2 + v3*v3;
            #pragma unroll
            for (int o = 16; o > 0; o >>= 1) {
                sum += __shfl_xor_sync(0xffffffffu, sum, o);
                sq  += __shfl_xor_sync(0xffffffffu, sq,  o);
            }
            float mean = sum * (1.0f/128.0f);
            float var  = sq  * (1.0f/128.0f) - mean * mean;
            float r = rsqrtf(var + 1e-5f);
            float o0 = (v0 - mean) * r * sc4.x + bc4.x;
            float o1 = (v1 - mean) * r * sc4.y + bc4.y;
            float o2 = (v2 - mean) * r * sc4.z + bc4.z;
            float o3 = (v3 - mean) * r * sc4.w + bc4.w;
            __half2* d = (__half2*)(smc + (lane >> 3) * CHB + row * SMSB + (lane & 7) * 8);
            d[0] = __floats2half2_rn(o0, o1);
            d[1] = __floats2half2_rn(o2, o3);
        }
    }

    const int lrow = (lane & 7) + ((lane >> 3) & 1) * 8;
    const int lk2  = ((lane >> 4) & 1) * 8;
    const int ra0  = (w & 3) * 32 + lrow;
    const int rb0  = (w >> 2) * 64 + lrow;

    float acc[2][8][4];
    const int nst = (N >> 7) * 4;
    for (int s = 0; s < nst; s++) {
        if (s + 2 < nst) {
            loadB(s + 2);
            asm volatile("cp.async.wait_group 2;\n" ::);
        } else if (s + 1 < nst) {
            asm volatile("cp.async.wait_group 1;\n" ::);
        } else {
            asm volatile("cp.async.wait_group 0;\n" ::);
        }
        __syncthreads();                  // publish B chunk s (and LN tile at s=0)
        if ((s & 3) == 0) {
            #pragma unroll
            for (int mi = 0; mi < 2; mi++)
                #pragma unroll
                for (int ni = 0; ni < 8; ni++)
                    #pragma unroll
                    for (int r = 0; r < 4; r++) acc[mi][ni][r] = 0.0f;
        }
        mma_tile16(sA + (uint32_t)((s & 3)*CHB), sB + (uint32_t)((s & 3)*CHB),
                   ra0, rb0, lk2, acc);
        if ((s & 3) == 3)
            epi12816<EPI, true>(acc, bias, nullptr, C, M, N, bm, (s >> 2) * 128,
                                w & 3, w >> 2, lane);
    }
}

// ---------------- fused attention + o-proj (+fp16 residual): N=128, K=128 ----------------
// All 4 B chunks load during attention; ONE sync; 4 uninterrupted mma chunks.
__global__ void __launch_bounds__(256, 2)
attn16(const __half* __restrict__ qkv, const __half* __restrict__ Bt,
       const float* __restrict__ bias, __half* __restrict__ H, int M) {
    extern __shared__ char smc[];
    const int tid  = threadIdx.x;
    const int lane = tid & 31;
    const int w    = tid >> 5;
    const int bm   = blockIdx.y * 128;

    const uint32_t sA = (uint32_t)__cvta_generic_to_shared(smc);
    const uint32_t sB = sA + 4*CHB;

    // all 4 B chunks up front (one commit)
    #pragma unroll
    for (int kc = 0; kc < 4; kc++) {
        #pragma unroll
        for (int l = 0; l < 2; l++) {
            int idx = tid + l * 256;
            int row = idx >> 2;
            int g   = idx & 3;
            cpasync16(sB + (uint32_t)(kc*CHB + row*SMSB + g*16),
                      Bt + (size_t)row * 128 + kc * 32 + g * 8, true);
        }
    }
    cp_commit();

    // attention: thread owns (point, head); writes 16 fp16 per token row into A tile
    {
        int p_local = tid >> 3;
        int hh = tid & 7;
        int p = (bm >> 2) + p_local;
        if (p < NP) {
            const __half* base = qkv + (size_t)p * 1536 + hh * 16;
            #pragma unroll
            for (int qi = 0; qi < 4; qi++) {
                float q[16];
                ld16h(base + qi * 384, q);
                float sc[4];
                float mx = -1e30f;
                #pragma unroll
                for (int ki = 0; ki < 4; ki++) {
                    float kv[16];
                    ld16h(base + 128 + ki * 384, kv);
                    float s = 0.0f;
                    #pragma unroll
                    for (int c = 0; c < 16; c++) s += q[c] * kv[c];
                    s *= 0.25f;
                    sc[ki] = s;
                    mx = fmaxf(mx, s);
                }
                float sum = 0.0f;
                #pragma unroll
                for (int ki = 0; ki < 4; ki++) { sc[ki] = expf(sc[ki] - mx); sum += sc[ki]; }
                float inv = 1.0f / sum;
                float acco[16];
                #pragma unroll
                for (int d = 0; d < 16; d++) acco[d] = 0.0f;
                #pragma unroll
                for (int ki = 0; ki < 4; ki++) {
                    float wv = sc[ki] * inv;
                    float vv[16];
                    ld16h(base + 256 + ki * 384, vv);
                    #pragma unroll
                    for (int c = 0; c < 16; c++) acco[c] += wv * vv[c];
                }
                int row = p_local * 4 + qi;
                __half2* d = (__half2*)(smc + (hh >> 1) * CHB + row * SMSB + (hh & 1) * 32);
                #pragma unroll
                for (int c = 0; c < 8; c++)
                    d[c] = __floats2half2_rn(acco[2*c], acco[2*c+1]);
            }
        } else {
            int p_l = tid >> 3, hh2 = tid & 7;
            #pragma unroll
            for (int qi = 0; qi < 4; qi++) {
                int row = p_l * 4 + qi;
                __half2* d = (__half2*)(smc + (hh2 >> 1) * CHB + row * SMSB + (hh2 & 1) * 32);
                #pragma unroll
                for (int c = 0; c < 8; c++) d[c] = __floats2half2_rn(0.0f, 0.0f);
            }
        }
    }

    asm volatile("cp.async.wait_group 0;\n" ::);
    __syncthreads();

    float acc[2][8][4];
    #pragma unroll
    for (int mi = 0; mi < 2; mi++)
        #pragma unroll
        for (int ni = 0; ni < 8; ni++)
            #pragma unroll
            for (int r = 0; r < 4; r++) acc[mi][ni][r] = 0.0f;

    const int lrow = (lane & 7) + ((lane >> 3) & 1) * 8;
    const int lk2  = ((lane >> 4) & 1) * 8;
    const int ra0  = (w & 3) * 32 + lrow;
    const int rb0  = (w >> 2) * 64 + lrow;

    #pragma unroll
    for (int kc = 0; kc < 4; kc++)
        mma_tile16(sA + (uint32_t)(kc*CHB), sB + (uint32_t)(kc*CHB),
                   ra0, rb0, lk2, acc);
    epi12816<1, true>(acc, bias, H, H, M, 128, bm, 0, w & 3, w >> 2, lane);
}

// ---------------- output init + final divide (vectorized) ----------------
__global__ void zero_kernel(float4* __restrict__ out) {
    int i = blockIdx.x * blockDim.x + threadIdx.x;
    int n4 = NCELL * CLN / 4;
    if (i < n4) out[i] = make_float4(0.f, 0.f, 0.f, 0.f);
    else if (i < n4 + NCELL) g_cnt[i - n4] = 0.0f;
}

__global__ void div_kernel(float4* __restrict__ out) {
    int i = blockIdx.x * blockDim.x + threadIdx.x;
    if (i >= NCELL * CLN / 4) return;
    float inv = 1.0f / fmaxf(g_cnt[i >> 7], 1.0f);
    float4 v = out[i];
    v.x *= inv; v.y *= inv; v.z *= inv; v.w *= inv;
    out[i] = v;
}

// ---------------- driver ----------------
extern "C" void kernel_launch(void* const* d_in, const int* in_sizes, int n_in,
                              void* d_out, int out_size) {
    const float* x      = (const float*)d_in[0];
    const float* W_emb  = (const float*)d_in[1];
    const float* b_emb  = (const float*)d_in[2];
    const float* ln1_s  = (const float*)d_in[3];
    const float* ln1_b  = (const float*)d_in[4];
    const float* Wqkv   = (const float*)d_in[5];
    const float* bqkv   = (const float*)d_in[6];
    const float* Wo     = (const float*)d_in[7];
    const float* bo     = (const float*)d_in[8];
    const float* ln2_s  = (const float*)d_in[9];
    const float* ln2_b  = (const float*)d_in[10];
    const float* Wf1    = (const float*)d_in[11];
    const float* bf1    = (const float*)d_in[12];
    const float* Wf2    = (const float*)d_in[13];
    const float* bf2    = (const float*)d_in[14];
    const float* W_comb = (const float*)d_in[15];
    const float* b_comb = (const float*)d_in[16];
    float* out = (float*)d_out;

    __half *p_feat, *p_h, *p_qkv, *p_gel, *p_wt;
    cudaGetSymbolAddress((void**)&p_feat, g_feat);
    cudaGetSymbolAddress((void**)&p_h,    g_h);
    cudaGetSymbolAddress((void**)&p_qkv,  g_qkv);
    cudaGetSymbolAddress((void**)&p_gel,  g_gel);
    cudaGetSymbolAddress((void**)&p_wt,   g_wt);

    const int SMEM = 8 * CHB;   // 81920
    static bool attr_done = false;
    if (!attr_done) {
        cudaFuncSetAttribute((const void*)gemm_tc16<0,true>,  cudaFuncAttributeMaxDynamicSharedMemorySize, SMEM);
        cudaFuncSetAttribute((const void*)gemm_tc16<1,true>,  cudaFuncAttributeMaxDynamicSharedMemorySize, SMEM);
        cudaFuncSetAttribute((const void*)gemm_tc16<3,false>, cudaFuncAttributeMaxDynamicSharedMemorySize, SMEM);
        cudaFuncSetAttribute((const void*)lnA16<0>, cudaFuncAttributeMaxDynamicSharedMemorySize, SMEM);
        cudaFuncSetAttribute((const void*)lnA16<2>, cudaFuncAttributeMaxDynamicSharedMemorySize, SMEM);
        cudaFuncSetAttribute((const void*)attn16,   cudaFuncAttributeMaxDynamicSharedMemorySize, SMEM);
        attr_done = true;
    }

    const int TB = 256;

    // fp16 weight offsets in g_wt
    __half* wembT  = p_wt + 0;        // [512][96]
    __half* wqkvT0 = p_wt + 49152;    // [384][128]
    __half* wqkvT1 = p_wt + 98304;
    __half* woT0   = p_wt + 147456;   // [128][128]
    __half* woT1   = p_wt + 163840;
    __half* wf1T0  = p_wt + 180224;   // [512][128]
    __half* wf1T1  = p_wt + 245760;
    __half* wf2T0  = p_wt + 311296;   // [128][512]
    __half* wf2T1  = p_wt + 376832;
    __half* wcombT = p_wt + 442368;   // [512][512]

    wconv<<<(704512 + TB - 1) / TB, TB>>>(W_emb, Wqkv, Wo, Wf1, Wf2, W_comb);
    // zero out + counts BEFORE feat (feat accumulates counts)
    zero_kernel<<<(NCELL * CLN / 4 + NCELL + TB - 1) / TB, TB>>>((float4*)out);
    feat_kernel<<<(NP + TB - 1) / TB, TB>>>(x);

    // embedding: feat(NP x 96 fp16) @ W_emb -> h (fp16)
    gemm_tc16<0,true><<<dim3(4, (NP + 127) / 128), TB, SMEM>>>(
        p_feat, wembT, b_emb, nullptr, p_h, NP, 512, 96, 96, 96);

    const __half* wqkvT[2] = {wqkvT0, wqkvT1};
    const __half* woT[2]   = {woT0, woT1};
    const __half* wf1T[2]  = {wf1T0, wf1T1};
    const __half* wf2T[2]  = {wf2T0, wf2T1};
    const int MB = (NTOK + 127) / 128;   // 2048

    for (int i = 0; i < 2; i++) {
        // LN1 + QKV -> fp16 qkv
        lnA16<0><<<dim3(1, MB), TB, SMEM>>>(p_h, wqkvT[i], bqkv + i * 384,
                                            ln1_s + i * 128, ln1_b + i * 128,
                                            p_qkv, NTOK, 384);
        // attention + o-proj + residual (h fp16)
        attn16<<<dim3(1, MB), TB, SMEM>>>(p_qkv, woT[i], bo + i * 128, p_h, NTOK);
        // LN2 + FF1 + GELU -> g_gel (fp16)
        lnA16<2><<<dim3(1, MB), TB, SMEM>>>(p_h, wf1T[i], bf1 + i * 512,
                                            ln2_s + i * 128, ln2_b + i * 128,
                                            p_gel, NTOK, 512);
        // FF2 + residual (h fp16)
        gemm_tc16<1,true><<<dim3(1, MB), TB, SMEM>>>(p_gel, wf2T[i], bf2 + i * 128,
                                                     p_h, p_h, NTOK, 128, 512, 512, 512);
    }

    // head: h(NP x 512 fp16) @ W_comb -> scattered directly into out (atomicAdd)
    gemm_tc16<3,false><<<dim3(4, (NP + 127) / 128), TB, SMEM>>>(
        p_h, wcombT, b_comb, nullptr, out, NP, 512, 512, 512, 512);

    // final divide by counts
    div_kernel<<<(NCELL * CLN / 4 + TB - 1) / TB, TB>>>((float4*)out);
}